// round 9
// baseline (speedup 1.0000x reference)
#include <cuda_runtime.h>
#include <mma.h>
#include <math.h>
#include <stdint.h>

using namespace nvcuda;

#define BB 256
#define PP 620
#define CC 512
#define TT 32
#define VV 140
#define HH 256
#define AA 256
#define KIH (VV + AA)         // 396
#define KTOT (VV + AA + HH)   // 652 : [x | ctx | h]
#define NG   (4 * HH)         // 1024 gates
#define PT   16               // attention p-tile rows
#define NTILE ((PP + PT - 1) / PT)   // 39

// ---------------- scratch (device globals; no allocations allowed) ----------
__device__ float g_attn[(size_t)BB * PP * AA];   // 162.5 MB
__device__ float g_h[BB * HH];
__device__ float g_c[BB * HH];
__device__ float g_x[BB * VV];
__device__ float g_ctx[BB * AA];
__device__ float g_gpart[4][BB * NG];            // split-K partials

// ---------------- helpers ----------------
__device__ __forceinline__ float warp_sum(float v) {
#pragma unroll
    for (int o = 16; o > 0; o >>= 1) v += __shfl_xor_sync(0xFFFFFFFFu, v, o);
    return v;
}
__device__ __forceinline__ float sigmoidf_(float x) { return 1.0f / (1.0f + __expf(-x)); }

#define CP_ASYNC16(dst32, src) \
    asm volatile("cp.async.cg.shared.global [%0], [%1], 16;" :: "r"(dst32), "l"(src))
#define CP_COMMIT() asm volatile("cp.async.commit_group;")
#define CP_WAIT(N)  asm volatile("cp.async.wait_group %0;" :: "n"(N))

// ============================================================================
// Kernel 1: projection  attn[m, a] = sum_c img[m, c] * Ic_w[a, c] + Ic_b[a]
// M = B*P = 158720, N = A = 256, K = C = 512.  tf32 wmma, 64x64 tile, kt=16.
// ============================================================================
__global__ void proj_kernel(const float* __restrict__ img,
                            const float* __restrict__ Icw,
                            const float* __restrict__ Icb) {
    __shared__ float smA[64 * 16];
    __shared__ float smB[64 * 16];
    __shared__ float st[64 * 64];

    const int bm = blockIdx.x * 64;
    const int bn = blockIdx.y * 64;
    const int tid = threadIdx.x;
    const int warp = tid >> 5;
    const int warp_m = warp & 3;
    const int warp_n = warp >> 2;

    wmma::fragment<wmma::accumulator, 16, 16, 8, float> acc[2];
    wmma::fill_fragment(acc[0], 0.0f);
    wmma::fill_fragment(acc[1], 0.0f);

    for (int k0 = 0; k0 < CC; k0 += 16) {
#pragma unroll
        for (int i = 0; i < 4; i++) {
            int idx = tid + i * 256;
            int r = idx >> 4, c = idx & 15;
            smA[idx] = wmma::__float_to_tf32(img[(size_t)(bm + r) * CC + k0 + c]);
            smB[idx] = wmma::__float_to_tf32(Icw[(size_t)(bn + r) * CC + k0 + c]);
        }
        __syncthreads();
#pragma unroll
        for (int kk = 0; kk < 16; kk += 8) {
            wmma::fragment<wmma::matrix_a, 16, 16, 8, wmma::precision::tf32, wmma::row_major> fa;
            wmma::load_matrix_sync(fa, smA + warp_m * 16 * 16 + kk, 16);
#pragma unroll
            for (int j = 0; j < 2; j++) {
                wmma::fragment<wmma::matrix_b, 16, 16, 8, wmma::precision::tf32, wmma::col_major> fb;
                wmma::load_matrix_sync(fb, smB + (warp_n * 32 + j * 16) * 16 + kk, 16);
                wmma::mma_sync(acc[j], fa, fb, acc[j]);
            }
        }
        __syncthreads();
    }

#pragma unroll
    for (int j = 0; j < 2; j++)
        wmma::store_matrix_sync(st + (warp_m * 16) * 64 + warp_n * 32 + j * 16,
                                acc[j], 64, wmma::mem_row_major);
    __syncthreads();

#pragma unroll
    for (int i = 0; i < 16; i++) {
        int idx = i * 256 + tid;
        int r = idx >> 6, c = idx & 63;
        g_attn[(size_t)(bm + r) * AA + bn + c] = st[idx] + Icb[bn + c];
    }
}

// ============================================================================
// Kernel 2: init  h=0, c=0, x = targets[:, 0, :]
// ============================================================================
__global__ void init_kernel(const float* __restrict__ targets) {
    int i = blockIdx.x * blockDim.x + threadIdx.x;
    if (i < BB * HH) { g_h[i] = 0.0f; g_c[i] = 0.0f; }
    if (i < BB * VV) {
        int b = i / VV, v = i % VV;
        g_x[i] = targets[(size_t)b * TT * VV + v];
    }
}

// ============================================================================
// Kernel 3: per-step attention — SINGLE PASS (online softmax + ctx accum).
// One block per b.  attn[b] (620x256, 635 KB) streamed ONCE through smem in
// 16-row tiles with cp.async double buffering.  ctx held in registers
// (thread tid owns column a = tid).
// ============================================================================
__global__ void attn_step_kernel(const float* __restrict__ Hcw,
                                 const float* __restrict__ Hcb) {
    const int b = blockIdx.x;
    const int tid = threadIdx.x;
    const int warp = tid >> 5, lane = tid & 31;

    __shared__ float buf[2][PT * AA];   // 2 x 16KB
    __shared__ float sh[HH];
    __shared__ float sq[AA];
    __shared__ float sraw[PT];
    __shared__ float se[PT];

    const float* attb = g_attn + (size_t)b * PP * AA;

    // -- issue prefetch of tiles 0 and 1 before anything else --
#pragma unroll
    for (int tl = 0; tl < 2; tl++) {
#pragma unroll
        for (int i = 0; i < 4; i++) {
            int idx = tid + i * 256;
            int row = idx >> 6, c4 = (idx & 63) * 4;
            int p = tl * PT + row;
            if (p < PP) {
                unsigned int dst = (unsigned int)__cvta_generic_to_shared(&buf[tl][row * AA + c4]);
                CP_ASYNC16(dst, attb + (size_t)p * AA + c4);
            }
        }
        CP_COMMIT();
    }

    // -- q = h[b] @ Hc_w^T + Hc_b (overlaps with the prefetch above) --
    sh[tid] = g_h[b * HH + tid];
    __syncthreads();
    for (int j = warp; j < AA; j += 8) {
        const float* wr = Hcw + (size_t)j * HH;
        float s = 0.0f;
#pragma unroll
        for (int k = lane; k < HH; k += 32) s += sh[k] * wr[k];
        s = warp_sum(s);
        if (lane == 0) sq[j] = s + Hcb[j];
    }
    __syncthreads();

    const float scale = 0.0625f;  // 1/sqrt(256)
    float m = -1e30f, ssum = 0.0f, ctx = 0.0f;

    for (int t = 0; t < NTILE; t++) {
        const int cur = t & 1;
        const int rows = min(PT, PP - t * PT);

        if (t + 1 < NTILE) { CP_WAIT(1); } else { CP_WAIT(0); }
        __syncthreads();

        // scores for this tile (warp per row)
        for (int r = warp; r < rows; r += 8) {
            const float* rowp = &buf[cur][r * AA];
            float s = 0.0f;
#pragma unroll
            for (int a = lane; a < AA; a += 32) s += sq[a] * rowp[a];
            s = warp_sum(s);
            if (lane == 0) sraw[r] = s * scale;
        }
        __syncthreads();

        // online-softmax update (all threads compute identical newm/fac)
        float tm = -1e30f;
#pragma unroll
        for (int r = 0; r < PT; r++) if (r < rows) tm = fmaxf(tm, sraw[r]);
        const float newm = fmaxf(m, tm);
        const float fac = expf(m - newm);
        if (warp == 0 && lane < rows) se[lane] = expf(sraw[lane] - newm);
        __syncthreads();

        ctx *= fac;
        ssum *= fac;
#pragma unroll
        for (int r = 0; r < PT; r++) {
            if (r < rows) {
                float e = se[r];
                ssum += e;
                ctx = fmaf(e, buf[cur][r * AA + tid], ctx);
            }
        }
        m = newm;
        __syncthreads();

        // refill the buffer we just finished with tile t+2
        if (t + 2 < NTILE) {
#pragma unroll
            for (int i = 0; i < 4; i++) {
                int idx = tid + i * 256;
                int row = idx >> 6, c4 = (idx & 63) * 4;
                int p = (t + 2) * PT + row;
                if (p < PP) {
                    unsigned int dst = (unsigned int)__cvta_generic_to_shared(&buf[cur][row * AA + c4]);
                    CP_ASYNC16(dst, attb + (size_t)p * AA + c4);
                }
            }
            CP_COMMIT();
        }
    }

    g_ctx[b * AA + tid] = ctx / ssum;
}

// ============================================================================
// Kernel 4: gates GEMM, split-K=4.
// gpart[z][b,n] = sum_{k in panels z::4} [x|ctx|h][b,k] * Wcat[n,k]
// Tile 64Mx64N, 256 threads, 4x4 per thread with float4 LDS. grid (4,16,4).
// ============================================================================
__global__ void gates_kernel(const float* __restrict__ Wih,
                             const float* __restrict__ Whh) {
    __shared__ float sA[16][72];   // [k][m], padded
    __shared__ float sB[16][72];   // [k][n]
    const int bm = blockIdx.x * 64;
    const int bn = blockIdx.y * 64;
    const int z  = blockIdx.z;
    const int tid = threadIdx.x;
    const int tm = tid & 15;       // 16 groups of 4 m
    const int tn = tid >> 4;       // 16 groups of 4 n

    float acc[4][4] = {};

    for (int panel = z; panel * 16 < KTOT; panel += 4) {
        const int k0 = panel * 16;
        // A tile: 64 m x 16 k  (gather from x|ctx|h), stored k-major
#pragma unroll
        for (int i = 0; i < 4; i++) {
            int idx = tid + i * 256;
            int mrow = idx >> 4, kk = idx & 15;
            int k = k0 + kk, brow = bm + mrow;
            float v = 0.0f;
            if (k < KTOT) {
                if (k < VV)       v = g_x[brow * VV + k];
                else if (k < KIH) v = g_ctx[brow * AA + (k - VV)];
                else              v = g_h[brow * HH + (k - KIH)];
            }
            sA[kk][mrow] = v;
        }
        // B tile: 64 n x 16 k
#pragma unroll
        for (int i = 0; i < 4; i++) {
            int idx = tid + i * 256;
            int nl = idx >> 4, kk = idx & 15;
            int k = k0 + kk, n = bn + nl;
            float v = 0.0f;
            if (k < KTOT) {
                if (k < KIH) v = Wih[(size_t)n * KIH + k];
                else         v = Whh[(size_t)n * HH + (k - KIH)];
            }
            sB[kk][nl] = v;
        }
        __syncthreads();
#pragma unroll
        for (int kk = 0; kk < 16; kk++) {
            float4 av = *(const float4*)&sA[kk][tm * 4];
            float4 bv = *(const float4*)&sB[kk][tn * 4];
            const float ar[4] = {av.x, av.y, av.z, av.w};
            const float br[4] = {bv.x, bv.y, bv.z, bv.w};
#pragma unroll
            for (int r = 0; r < 4; r++)
#pragma unroll
                for (int c = 0; c < 4; c++)
                    acc[r][c] = fmaf(ar[r], br[c], acc[r][c]);
        }
        __syncthreads();
    }

    float* gp = g_gpart[z];
#pragma unroll
    for (int r = 0; r < 4; r++) {
        int row = bm + tm * 4 + r;
#pragma unroll
        for (int c = 0; c < 4; c++)
            gp[row * NG + bn + tn * 4 + c] = acc[r][c];
    }
}

// ============================================================================
// Kernel 5: combine split-K partials + biases, LSTM pointwise, output proj.
// One block per b (256 threads).  Writes out[:, t, :] and x_next = out.
// ============================================================================
__global__ void lstm_out_kernel(const float* __restrict__ bih,
                                const float* __restrict__ bhh,
                                const float* __restrict__ Cdw,
                                const float* __restrict__ Cdb,
                                float* __restrict__ out, int t) {
    const int b = blockIdx.x;
    const int tid = threadIdx.x;
    const int warp = tid >> 5, lane = tid & 31;
    __shared__ float sh2[HH];

    const int base = b * NG;
    float gi = bih[tid]       + bhh[tid];
    float gf = bih[256 + tid] + bhh[256 + tid];
    float gg = bih[512 + tid] + bhh[512 + tid];
    float go = bih[768 + tid] + bhh[768 + tid];
#pragma unroll
    for (int z = 0; z < 4; z++) {
        const float* gp = g_gpart[z] + base;
        gi += gp[tid];
        gf += gp[256 + tid];
        gg += gp[512 + tid];
        go += gp[768 + tid];
    }

    float c2 = sigmoidf_(gf) * g_c[b * HH + tid] + sigmoidf_(gi) * tanhf(gg);
    float h2 = sigmoidf_(go) * tanhf(c2);
    g_c[b * HH + tid] = c2;
    g_h[b * HH + tid] = h2;
    sh2[tid] = h2;
    __syncthreads();

    for (int v = warp; v < VV; v += 8) {
        const float* wr = Cdw + (size_t)v * HH;
        float s = 0.0f;
#pragma unroll
        for (int k = lane; k < HH; k += 32) s += sh2[k] * wr[k];
        s = warp_sum(s);
        if (lane == 0) {
            float val = s + Cdb[v];
            out[((size_t)b * TT + t) * VV + v] = val;
            g_x[b * VV + v] = val;
        }
    }
}

// ============================================================================
extern "C" void kernel_launch(void* const* d_in, const int* in_sizes, int n_in,
                              void* d_out, int out_size) {
    (void)in_sizes; (void)n_in; (void)out_size;
    const float* img  = (const float*)d_in[0];
    const float* tgt  = (const float*)d_in[1];
    const float* Icw  = (const float*)d_in[2];
    const float* Icb  = (const float*)d_in[3];
    const float* Hcw  = (const float*)d_in[4];
    const float* Hcb  = (const float*)d_in[5];
    const float* Wih  = (const float*)d_in[6];
    const float* Whh  = (const float*)d_in[7];
    const float* bih  = (const float*)d_in[8];
    const float* bhh  = (const float*)d_in[9];
    const float* Cdw  = (const float*)d_in[10];
    const float* Cdb  = (const float*)d_in[11];
    float* out = (float*)d_out;

    proj_kernel<<<dim3((BB * PP) / 64, AA / 64), 256>>>(img, Icw, Icb);
    init_kernel<<<(BB * HH + 255) / 256, 256>>>(tgt);

    for (int t = 0; t < TT; t++) {
        attn_step_kernel<<<BB, 256>>>(Hcw, Hcb);
        gates_kernel<<<dim3(BB / 64, NG / 64, 4), 256>>>(Wih, Whh);
        lstm_out_kernel<<<BB, 256>>>(bih, bhh, Cdw, Cdb, out, t);
    }
}

// round 10
// speedup vs baseline: 1.8492x; 1.8492x over previous
#include <cuda_runtime.h>
#include <cuda_fp16.h>
#include <mma.h>
#include <math.h>
#include <stdint.h>

using namespace nvcuda;

#define BB 256
#define PP 620
#define CC 512
#define TT 32
#define VV 140
#define HH 256
#define AA 256
#define KIH (VV + AA)         // 396
#define KTOT (VV + AA + HH)   // 652 : [x | ctx | h]
#define NG   (4 * HH)         // 1024 gates
#define NS   4                // attention cp.async ring depth (pairs of rows)

// ---------------- scratch (device globals; no allocations allowed) ----------
__device__ __half g_attn[(size_t)BB * PP * AA];   // 81.3 MB (fp16) — L2-resident
__device__ float  g_inp[BB * KTOT];               // packed [x | ctx | h]
__device__ float  g_c[BB * HH];
__device__ float  g_q[BB * AA];
__device__ float  g_gpart[4][BB * NG];            // split-K partials

// ---------------- helpers ----------------
__device__ __forceinline__ float warp_sum(float v) {
#pragma unroll
    for (int o = 16; o > 0; o >>= 1) v += __shfl_xor_sync(0xFFFFFFFFu, v, o);
    return v;
}
__device__ __forceinline__ float sigmoidf_(float x) { return 1.0f / (1.0f + __expf(-x)); }
__device__ __forceinline__ unsigned smem_u32(const void* p) {
    return (unsigned)__cvta_generic_to_shared(p);
}
__device__ __forceinline__ void load8h(float* v, const __half* p) {
    uint4 u = *(const uint4*)p;
    float2 f;
    f = __half22float2(*reinterpret_cast<__half2*>(&u.x)); v[0] = f.x; v[1] = f.y;
    f = __half22float2(*reinterpret_cast<__half2*>(&u.y)); v[2] = f.x; v[3] = f.y;
    f = __half22float2(*reinterpret_cast<__half2*>(&u.z)); v[4] = f.x; v[5] = f.y;
    f = __half22float2(*reinterpret_cast<__half2*>(&u.w)); v[6] = f.x; v[7] = f.y;
}

#define CP_ASYNC16(dst32, src) \
    asm volatile("cp.async.cg.shared.global [%0], [%1], 16;" :: "r"(dst32), "l"(src))
#define CP_COMMIT() asm volatile("cp.async.commit_group;")
#define CP_WAIT(N)  asm volatile("cp.async.wait_group %0;" :: "n"(N))

// ============================================================================
// Kernel 1: projection  attn[m, a] = sum_c img[m, c] * Ic_w[a, c] + Ic_b[a]
// M = B*P = 158720, N = A = 256, K = C = 512.  tf32 wmma, 64x64 tile.
// Output stored as fp16 (halves store traffic; keeps it L2-resident).
// ============================================================================
__global__ void proj_kernel(const float* __restrict__ img,
                            const float* __restrict__ Icw,
                            const float* __restrict__ Icb) {
    __shared__ float smA[64 * 16];
    __shared__ float smB[64 * 16];
    __shared__ float st[64 * 64];

    const int bm = blockIdx.x * 64;
    const int bn = blockIdx.y * 64;
    const int tid = threadIdx.x;
    const int warp = tid >> 5;
    const int warp_m = warp & 3;
    const int warp_n = warp >> 2;

    wmma::fragment<wmma::accumulator, 16, 16, 8, float> acc[2];
    wmma::fill_fragment(acc[0], 0.0f);
    wmma::fill_fragment(acc[1], 0.0f);

    for (int k0 = 0; k0 < CC; k0 += 16) {
#pragma unroll
        for (int i = 0; i < 4; i++) {
            int idx = tid + i * 256;
            int r = idx >> 4, c = idx & 15;
            smA[idx] = wmma::__float_to_tf32(img[(size_t)(bm + r) * CC + k0 + c]);
            smB[idx] = wmma::__float_to_tf32(Icw[(size_t)(bn + r) * CC + k0 + c]);
        }
        __syncthreads();
#pragma unroll
        for (int kk = 0; kk < 16; kk += 8) {
            wmma::fragment<wmma::matrix_a, 16, 16, 8, wmma::precision::tf32, wmma::row_major> fa;
            wmma::load_matrix_sync(fa, smA + warp_m * 16 * 16 + kk, 16);
#pragma unroll
            for (int j = 0; j < 2; j++) {
                wmma::fragment<wmma::matrix_b, 16, 16, 8, wmma::precision::tf32, wmma::col_major> fb;
                wmma::load_matrix_sync(fb, smB + (warp_n * 32 + j * 16) * 16 + kk, 16);
                wmma::mma_sync(acc[j], fa, fb, acc[j]);
            }
        }
        __syncthreads();
    }

#pragma unroll
    for (int j = 0; j < 2; j++)
        wmma::store_matrix_sync(st + (warp_m * 16) * 64 + warp_n * 32 + j * 16,
                                acc[j], 64, wmma::mem_row_major);
    __syncthreads();

    // write as half2 (2048 half2 / 256 threads = 8 iters)
#pragma unroll
    for (int i = 0; i < 8; i++) {
        int idx = i * 256 + tid;
        int r = idx >> 5, c2 = idx & 31;
        float v0 = st[r * 64 + 2 * c2]     + Icb[bn + 2 * c2];
        float v1 = st[r * 64 + 2 * c2 + 1] + Icb[bn + 2 * c2 + 1];
        __half2* dst = (__half2*)(g_attn + (size_t)(bm + r) * AA + bn);
        dst[c2] = __floats2half2_rn(v0, v1);
    }
}

// ============================================================================
// Kernel 2: init  g_inp = [x0 | 0 | 0], c = 0.   One block per b.
// ============================================================================
__global__ void init_kernel(const float* __restrict__ targets) {
    const int b = blockIdx.x;
    const int tid = threadIdx.x;
    for (int k = tid; k < KTOT; k += 256)
        g_inp[b * KTOT + k] = (k < VV) ? targets[(size_t)b * TT * VV + k] : 0.0f;
    g_c[b * HH + tid] = 0.0f;
}

// ============================================================================
// Kernel 3: q = h @ Hc_w^T + Hc_b.   32x32 tiles, grid (8, 8), 256 threads.
// h read from g_inp[:, KIH:].
// ============================================================================
__global__ void q_kernel(const float* __restrict__ Hcw,
                         const float* __restrict__ Hcb) {
    __shared__ float sH[64][33];   // [k][m]
    __shared__ float sW[64][33];   // [k][a]
    const int bm = blockIdx.x * 32;
    const int bn = blockIdx.y * 32;
    const int tid = threadIdx.x;
    const int a = tid & 31;        // lane
    const int mg = tid >> 5;       // warp id -> 4 m rows

    float acc[4] = {0.f, 0.f, 0.f, 0.f};

    for (int k0 = 0; k0 < HH; k0 += 64) {
#pragma unroll
        for (int i = 0; i < 2; i++) {
            int q = tid + i * 256;
            int mm = q >> 4, kq = q & 15;
            float4 hv = *(const float4*)&g_inp[(bm + mm) * KTOT + KIH + k0 + kq * 4];
            float4 wv = *(const float4*)&Hcw[(size_t)(bn + mm) * HH + k0 + kq * 4];
            sH[kq * 4 + 0][mm] = hv.x; sH[kq * 4 + 1][mm] = hv.y;
            sH[kq * 4 + 2][mm] = hv.z; sH[kq * 4 + 3][mm] = hv.w;
            sW[kq * 4 + 0][mm] = wv.x; sW[kq * 4 + 1][mm] = wv.y;
            sW[kq * 4 + 2][mm] = wv.z; sW[kq * 4 + 3][mm] = wv.w;
        }
        __syncthreads();
#pragma unroll
        for (int kk = 0; kk < 64; kk++) {
            float w = sW[kk][a];
#pragma unroll
            for (int r = 0; r < 4; r++)
                acc[r] = fmaf(sH[kk][mg * 4 + r], w, acc[r]);
        }
        __syncthreads();
    }
    float bias = Hcb[bn + a];
#pragma unroll
    for (int r = 0; r < 4; r++)
        g_q[(bm + mg * 4 + r) * AA + bn + a] = acc[r] + bias;
}

// ============================================================================
// Kernel 4: attention — warp-autonomous single-pass flash softmax.
// One CTA per b; warp w owns rows p = w + 8i.  Each lane's 16B cp.async chunk
// is exactly the 8 columns it accumulates ctx for: NO cross-lane smem reads,
// NO block barriers in the mainloop.  Per-lane 4-deep cp.async ring (2 rows
// per stage).  Final 8-warp merge via smem.
// ============================================================================
__global__ void attn_kernel() {
    __shared__ __align__(16) __half abuf[8][NS][2][AA];  // 32 KB
    __shared__ float cbuf[8][AA];                        // 8 KB
    __shared__ float sm_m[8], sm_s[8];

    const int b = blockIdx.x;
    const int tid = threadIdx.x;
    const int w = tid >> 5, l = tid & 31;
    const __half* attb = g_attn + (size_t)b * PP * AA;

    const int nrow = (PP - w + 7) >> 3;     // 78 (w<4) or 77
    const int npair = (nrow + 1) >> 1;      // 39

    // prologue: issue NS pair-stages
#pragma unroll
    for (int it = 0; it < NS; it++) {
        int i0 = 2 * it, i1 = i0 + 1;
        CP_ASYNC16(smem_u32(&abuf[w][it][0][l * 8]), attb + (size_t)(w + i0 * 8) * AA + l * 8);
        if (i1 < nrow)
            CP_ASYNC16(smem_u32(&abuf[w][it][1][l * 8]), attb + (size_t)(w + i1 * 8) * AA + l * 8);
        CP_COMMIT();
    }

    // q chunk for this lane (the 8 columns it owns)
    float q8[8];
    {
        float4 qa = *(const float4*)&g_q[b * AA + l * 8];
        float4 qb = *(const float4*)&g_q[b * AA + l * 8 + 4];
        q8[0] = qa.x; q8[1] = qa.y; q8[2] = qa.z; q8[3] = qa.w;
        q8[4] = qb.x; q8[5] = qb.y; q8[6] = qb.z; q8[7] = qb.w;
    }

    const float scale = 0.0625f;  // 1/sqrt(256)
    float m = -1e30f, ssum = 0.0f;
    float ctx[8] = {0.f, 0.f, 0.f, 0.f, 0.f, 0.f, 0.f, 0.f};

    for (int it = 0; it < npair; it++) {
        const int s = it & (NS - 1);
        CP_WAIT(NS - 1);

        float v0[8], v1[8];
        load8h(v0, &abuf[w][s][0][l * 8]);
        load8h(v1, &abuf[w][s][1][l * 8]);

        float d0 = 0.f, d1 = 0.f;
#pragma unroll
        for (int j = 0; j < 8; j++) { d0 = fmaf(q8[j], v0[j], d0); d1 = fmaf(q8[j], v1[j], d1); }
        d0 = warp_sum(d0);
        d1 = warp_sum(d1);

        const bool val1 = (2 * it + 1) < nrow;   // warp-uniform
        float sc0 = d0 * scale;
        float sc1 = val1 ? d1 * scale : -1e30f;
        float mn = fmaxf(m, fmaxf(sc0, sc1));
        float fac = __expf(m - mn);
        float e0 = __expf(sc0 - mn);
        float e1 = val1 ? __expf(sc1 - mn) : 0.0f;
        ssum = ssum * fac + e0 + e1;
        if (val1) {
#pragma unroll
            for (int j = 0; j < 8; j++)
                ctx[j] = fmaf(e1, v1[j], fmaf(e0, v0[j], ctx[j] * fac));
        } else {
#pragma unroll
            for (int j = 0; j < 8; j++)
                ctx[j] = fmaf(e0, v0[j], ctx[j] * fac);
        }
        m = mn;

        // refill stage s with pair it+NS
        int nit = it + NS;
        if (nit < npair) {
            int i0 = 2 * nit, i1 = i0 + 1;
            CP_ASYNC16(smem_u32(&abuf[w][s][0][l * 8]), attb + (size_t)(w + i0 * 8) * AA + l * 8);
            if (i1 < nrow)
                CP_ASYNC16(smem_u32(&abuf[w][s][1][l * 8]), attb + (size_t)(w + i1 * 8) * AA + l * 8);
        }
        CP_COMMIT();
    }

    // merge 8 warps
    *(float4*)&cbuf[w][l * 8]     = make_float4(ctx[0], ctx[1], ctx[2], ctx[3]);
    *(float4*)&cbuf[w][l * 8 + 4] = make_float4(ctx[4], ctx[5], ctx[6], ctx[7]);
    if (l == 0) { sm_m[w] = m; sm_s[w] = ssum; }
    __syncthreads();

    const int a = tid;
    float M = -1e30f;
#pragma unroll
    for (int ww = 0; ww < 8; ww++) M = fmaxf(M, sm_m[ww]);
    float S = 0.f, C = 0.f;
#pragma unroll
    for (int ww = 0; ww < 8; ww++) {
        float ef = __expf(sm_m[ww] - M);
        S += ef * sm_s[ww];
        C = fmaf(ef, cbuf[ww][a], C);
    }
    g_inp[b * KTOT + VV + a] = C / S;
}

// ============================================================================
// Kernel 5: gates GEMM, split-K=4, register-prefetch double buffering.
// gpart[z][b,n] = sum_{k in panels z::4} inp[b,k] * Wcat[n,k]
// 64x64 tile, 256 threads, 4x4 per-thread, grid (4, 16, 4).
// ============================================================================
__global__ void gates_kernel(const float* __restrict__ Wih,
                             const float* __restrict__ Whh) {
    __shared__ float sA[16][68];   // [k][m]
    __shared__ float sB[16][68];   // [k][n]
    const int bm = blockIdx.x * 64;
    const int bn = blockIdx.y * 64;
    const int z  = blockIdx.z;
    const int tid = threadIdx.x;
    const int tm = tid & 15;
    const int tn = tid >> 4;
    const int lrow = tid >> 2;     // 0..63 (m or n row this thread loads)
    const int kc   = tid & 3;      // k-quad within panel

    float acc[4][4] = {};
    float4 aReg, bReg;

    // ---- load panel helper (inlined twice) ----
    auto load_panel = [&](int k0) {
        int k = k0 + kc * 4;
        if (k + 3 < KTOT) {
            aReg = *(const float4*)&g_inp[(bm + lrow) * KTOT + k];
            if (k + 3 < KIH)
                bReg = *(const float4*)&Wih[(size_t)(bn + lrow) * KIH + k];
            else
                bReg = *(const float4*)&Whh[(size_t)(bn + lrow) * HH + (k - KIH)];
        } else {
            aReg = make_float4(0.f, 0.f, 0.f, 0.f);
            bReg = make_float4(0.f, 0.f, 0.f, 0.f);
        }
    };

    load_panel(z * 16);

    for (int panel = z; panel * 16 < KTOT; panel += 4) {
        // store prefetched regs to smem
        sA[kc * 4 + 0][lrow] = aReg.x; sA[kc * 4 + 1][lrow] = aReg.y;
        sA[kc * 4 + 2][lrow] = aReg.z; sA[kc * 4 + 3][lrow] = aReg.w;
        sB[kc * 4 + 0][lrow] = bReg.x; sB[kc * 4 + 1][lrow] = bReg.y;
        sB[kc * 4 + 2][lrow] = bReg.z; sB[kc * 4 + 3][lrow] = bReg.w;
        __syncthreads();

        // issue next panel's loads early (latency hidden by compute below)
        if ((panel + 4) * 16 < KTOT) load_panel((panel + 4) * 16);

#pragma unroll
        for (int kk = 0; kk < 16; kk++) {
            float4 av = *(const float4*)&sA[kk][tm * 4];
            float4 bv = *(const float4*)&sB[kk][tn * 4];
            const float ar[4] = {av.x, av.y, av.z, av.w};
            const float br[4] = {bv.x, bv.y, bv.z, bv.w};
#pragma unroll
            for (int r = 0; r < 4; r++)
#pragma unroll
                for (int c = 0; c < 4; c++)
                    acc[r][c] = fmaf(ar[r], br[c], acc[r][c]);
        }
        __syncthreads();
    }

    float* gp = g_gpart[z];
#pragma unroll
    for (int r = 0; r < 4; r++) {
        int row = bm + tm * 4 + r;
        *(float4*)&gp[row * NG + bn + tn * 4] =
            make_float4(acc[r][0], acc[r][1], acc[r][2], acc[r][3]);
    }
}

// ============================================================================
// Kernel 6: combine split-K partials + biases, LSTM pointwise, output proj.
// Writes out[:, t, :], and x/h into g_inp for the next step.
// ============================================================================
__global__ void lstm_out_kernel(const float* __restrict__ bih,
                                const float* __restrict__ bhh,
                                const float* __restrict__ Cdw,
                                const float* __restrict__ Cdb,
                                float* __restrict__ out, int t) {
    const int b = blockIdx.x;
    const int tid = threadIdx.x;
    const int warp = tid >> 5, lane = tid & 31;
    __shared__ float sh2[HH];

    const int base = b * NG;
    float gi = bih[tid]       + bhh[tid];
    float gf = bih[256 + tid] + bhh[256 + tid];
    float gg = bih[512 + tid] + bhh[512 + tid];
    float go = bih[768 + tid] + bhh[768 + tid];
#pragma unroll
    for (int z = 0; z < 4; z++) {
        const float* gp = g_gpart[z] + base;
        gi += gp[tid];
        gf += gp[256 + tid];
        gg += gp[512 + tid];
        go += gp[768 + tid];
    }

    float c2 = sigmoidf_(gf) * g_c[b * HH + tid] + sigmoidf_(gi) * tanhf(gg);
    float h2 = sigmoidf_(go) * tanhf(c2);
    g_c[b * HH + tid] = c2;
    g_inp[b * KTOT + KIH + tid] = h2;   // h for next step
    sh2[tid] = h2;
    __syncthreads();

    for (int v = warp; v < VV; v += 8) {
        const float* wr = Cdw + (size_t)v * HH;
        float s = 0.0f;
#pragma unroll
        for (int k = lane; k < HH; k += 32) s += sh2[k] * wr[k];
        s = warp_sum(s);
        if (lane == 0) {
            float val = s + Cdb[v];
            out[((size_t)b * TT + t) * VV + v] = val;
            g_inp[b * KTOT + v] = val;  // x for next step
        }
    }
}

// ============================================================================
extern "C" void kernel_launch(void* const* d_in, const int* in_sizes, int n_in,
                              void* d_out, int out_size) {
    (void)in_sizes; (void)n_in; (void)out_size;
    const float* img  = (const float*)d_in[0];
    const float* tgt  = (const float*)d_in[1];
    const float* Icw  = (const float*)d_in[2];
    const float* Icb  = (const float*)d_in[3];
    const float* Hcw  = (const float*)d_in[4];
    const float* Hcb  = (const float*)d_in[5];
    const float* Wih  = (const float*)d_in[6];
    const float* Whh  = (const float*)d_in[7];
    const float* bih  = (const float*)d_in[8];
    const float* bhh  = (const float*)d_in[9];
    const float* Cdw  = (const float*)d_in[10];
    const float* Cdb  = (const float*)d_in[11];
    float* out = (float*)d_out;

    proj_kernel<<<dim3((BB * PP) / 64, AA / 64), 256>>>(img, Icw, Icb);
    init_kernel<<<BB, 256>>>(tgt);

    for (int t = 0; t < TT; t++) {
        q_kernel<<<dim3(BB / 32, AA / 32), 256>>>(Hcw, Hcb);
        attn_kernel<<<BB, 256>>>();
        gates_kernel<<<dim3(BB / 64, NG / 64, 4), 256>>>(Wih, Whh);
        lstm_out_kernel<<<BB, 256>>>(bih, bhh, Cdw, Cdb, out, t);
    }
}

// round 11
// speedup vs baseline: 1.9044x; 1.0298x over previous
#include <cuda_runtime.h>
#include <cuda_fp16.h>
#include <mma.h>
#include <math.h>
#include <stdint.h>

using namespace nvcuda;

#define BB 256
#define PP 620
#define CC 512
#define TT 32
#define VV 140
#define HH 256
#define AA 256
#define KIH (VV + AA)         // 396
#define KTOT (VV + AA + HH)   // 652 : [x | ctx | h]
#define NG   (4 * HH)         // 1024 gates
#define NS   4                // attention cp.async ring depth (pair-stages)
#define NW   16               // attention warps per CTA
#define SPK  8                // gates split-K factor

// ---------------- scratch (device globals; no allocations allowed) ----------
__device__ __half g_attn[(size_t)BB * PP * AA];   // 81.3 MB (fp16)
__device__ float  g_inp[BB * KTOT];               // packed [x | ctx | h]
__device__ float  g_c[BB * HH];
__device__ float  g_q[BB * AA];
__device__ float  g_gpart[SPK][BB * NG];          // split-K partials

// ---------------- helpers ----------------
__device__ __forceinline__ float warp_sum(float v) {
#pragma unroll
    for (int o = 16; o > 0; o >>= 1) v += __shfl_xor_sync(0xFFFFFFFFu, v, o);
    return v;
}
__device__ __forceinline__ float sigmoidf_(float x) { return 1.0f / (1.0f + __expf(-x)); }
__device__ __forceinline__ unsigned smem_u32(const void* p) {
    return (unsigned)__cvta_generic_to_shared(p);
}
__device__ __forceinline__ void load8h(float* v, const __half* p) {
    uint4 u = *(const uint4*)p;
    float2 f;
    f = __half22float2(*reinterpret_cast<__half2*>(&u.x)); v[0] = f.x; v[1] = f.y;
    f = __half22float2(*reinterpret_cast<__half2*>(&u.y)); v[2] = f.x; v[3] = f.y;
    f = __half22float2(*reinterpret_cast<__half2*>(&u.z)); v[4] = f.x; v[5] = f.y;
    f = __half22float2(*reinterpret_cast<__half2*>(&u.w)); v[6] = f.x; v[7] = f.y;
}

#define CP_ASYNC16(dst32, src) \
    asm volatile("cp.async.cg.shared.global [%0], [%1], 16;" :: "r"(dst32), "l"(src))
#define CP_COMMIT() asm volatile("cp.async.commit_group;")
#define CP_WAIT(N)  asm volatile("cp.async.wait_group %0;" :: "n"(N))

// ============================================================================
// Kernel 1: projection  attn[m, a] = sum_c img[m, c] * Ic_w[a, c] + Ic_b[a]
// Tile 64M x 256N (FULL N -> img read exactly once), kt=16, double-buffered
// cp.async, tf32 wmma.  8 warps, each owns 64m x 32n (4x2 fragments).
// Epilogue: per-warp 16x16 patch -> +bias -> fp16 stores.
// ============================================================================
__global__ __launch_bounds__(256) void proj_kernel(const float* __restrict__ img,
                                                   const float* __restrict__ Icw,
                                                   const float* __restrict__ Icb) {
    __shared__ float smA[2][64 * 16];     // [m][k]   4KB x2
    __shared__ float smB[2][256 * 16];    // [n][k]  16KB x2
    __shared__ float patch[8][16 * 16];   // per-warp staging, 8KB

    const int bm = blockIdx.x * 64;
    const int tid = threadIdx.x;
    const int warp = tid >> 5, lane = tid & 31;

    const int NKS = CC / 16;  // 32 k-stages

    // ---- issue loads for stage ks into buffer buf ----
    auto issue = [&](int ks, int buf) {
        const int k0 = ks * 16;
        {   // A: 64x16 = 256 float4, 1 per thread
            int r = tid >> 2, q = tid & 3;
            CP_ASYNC16(smem_u32(&smA[buf][r * 16 + q * 4]),
                       img + (size_t)(bm + r) * CC + k0 + q * 4);
        }
#pragma unroll
        for (int i = 0; i < 4; i++) {  // B: 256x16 = 1024 float4, 4 per thread
            int idx = tid + i * 256;
            int n = idx >> 2, q = idx & 3;
            CP_ASYNC16(smem_u32(&smB[buf][n * 16 + q * 4]),
                       Icw + (size_t)n * CC + k0 + q * 4);
        }
        CP_COMMIT();
    };

    wmma::fragment<wmma::accumulator, 16, 16, 8, float> acc[4][2];
#pragma unroll
    for (int mi = 0; mi < 4; mi++)
#pragma unroll
        for (int nj = 0; nj < 2; nj++) wmma::fill_fragment(acc[mi][nj], 0.0f);

    issue(0, 0);
    issue(1, 1);

    for (int ks = 0; ks < NKS; ks++) {
        if (ks + 1 < NKS) { CP_WAIT(1); } else { CP_WAIT(0); }
        __syncthreads();
        const int buf = ks & 1;
#pragma unroll
        for (int kk = 0; kk < 16; kk += 8) {
            wmma::fragment<wmma::matrix_a, 16, 16, 8, wmma::precision::tf32, wmma::row_major> fa[4];
#pragma unroll
            for (int mi = 0; mi < 4; mi++)
                wmma::load_matrix_sync(fa[mi], &smA[buf][(mi * 16) * 16 + kk], 16);
#pragma unroll
            for (int nj = 0; nj < 2; nj++) {
                wmma::fragment<wmma::matrix_b, 16, 16, 8, wmma::precision::tf32, wmma::col_major> fb;
                wmma::load_matrix_sync(fb, &smB[buf][(warp * 32 + nj * 16) * 16 + kk], 16);
#pragma unroll
                for (int mi = 0; mi < 4; mi++)
                    wmma::mma_sync(acc[mi][nj], fa[mi], fb, acc[mi][nj]);
            }
        }
        __syncthreads();
        if (ks + 2 < NKS) issue(ks + 2, buf);
    }

    // ---- epilogue: frag -> patch -> +bias -> fp16 global ----
    const int prow = lane >> 1, pc0 = (lane & 1) * 8;
#pragma unroll
    for (int mi = 0; mi < 4; mi++) {
#pragma unroll
        for (int nj = 0; nj < 2; nj++) {
            wmma::store_matrix_sync(&patch[warp][0], acc[mi][nj], 16, wmma::mem_row_major);
            __syncwarp();
            const int gm = bm + mi * 16 + prow;
            const int gc = warp * 32 + nj * 16 + pc0;
            __half2 h2s[4];
#pragma unroll
            for (int j = 0; j < 4; j++) {
                float v0 = patch[warp][prow * 16 + pc0 + 2 * j]     + Icb[gc + 2 * j];
                float v1 = patch[warp][prow * 16 + pc0 + 2 * j + 1] + Icb[gc + 2 * j + 1];
                h2s[j] = __floats2half2_rn(v0, v1);
            }
            *(uint4*)&g_attn[(size_t)gm * AA + gc] = *(uint4*)h2s;
            __syncwarp();
        }
    }
}

// ============================================================================
// Kernel 2: init  g_inp = [x0 | 0 | 0], c = 0, q0 = Hc_b (since h0 = 0).
// ============================================================================
__global__ void init_kernel(const float* __restrict__ targets,
                            const float* __restrict__ Hcb) {
    const int b = blockIdx.x;
    const int tid = threadIdx.x;
    for (int k = tid; k < KTOT; k += 256)
        g_inp[b * KTOT + k] = (k < VV) ? targets[(size_t)b * TT * VV + k] : 0.0f;
    g_c[b * HH + tid] = 0.0f;
    g_q[b * AA + tid] = Hcb[tid];
}

// ============================================================================
// Kernel 3: attention — warp-autonomous single-pass flash softmax.
// 512 threads (16 warps) per CTA, one CTA per b.  Warp w owns rows
// p = w + 16i.  Each lane's 16B cp.async chunk is exactly the 8 columns it
// accumulates ctx for: no cross-lane smem traffic, no block barriers in the
// mainloop.  4-deep per-warp cp.async ring (2 rows/stage).  Dynamic smem
// 64 KB; cbuf for the 16-warp merge aliases the ring buffer.
// ============================================================================
__global__ __launch_bounds__(512) void attn_kernel() {
    extern __shared__ __align__(16) char dynsm[];
    __half (*abuf)[NS][2][AA] = (__half (*)[NS][2][AA])dynsm;  // [NW][NS][2][AA]
    float* cbuf = (float*)dynsm;                               // reused: [NW][AA]
    __shared__ float sm_m[NW], sm_s[NW];

    const int b = blockIdx.x;
    const int tid = threadIdx.x;
    const int w = tid >> 5, l = tid & 31;
    const __half* attb = g_attn + (size_t)b * PP * AA;

    const int nrow = (PP - w + 15) >> 4;    // 39 (w<=11) or 38
    const int npair = (nrow + 1) >> 1;      // 20 or 19

    // prologue: NS pair-stages (rows 0..7 of this warp always exist)
#pragma unroll
    for (int it = 0; it < NS; it++) {
        CP_ASYNC16(smem_u32(&abuf[w][it][0][l * 8]),
                   attb + (size_t)(w + (2 * it) * NW) * AA + l * 8);
        CP_ASYNC16(smem_u32(&abuf[w][it][1][l * 8]),
                   attb + (size_t)(w + (2 * it + 1) * NW) * AA + l * 8);
        CP_COMMIT();
    }

    float q8[8];
    {
        float4 qa = *(const float4*)&g_q[b * AA + l * 8];
        float4 qb = *(const float4*)&g_q[b * AA + l * 8 + 4];
        q8[0] = qa.x; q8[1] = qa.y; q8[2] = qa.z; q8[3] = qa.w;
        q8[4] = qb.x; q8[5] = qb.y; q8[6] = qb.z; q8[7] = qb.w;
    }

    const float scale = 0.0625f;  // 1/sqrt(256)
    float m = -1e30f, ssum = 0.0f;
    float ctx[8] = {0.f, 0.f, 0.f, 0.f, 0.f, 0.f, 0.f, 0.f};

    for (int it = 0; it < npair; it++) {
        const int s = it & (NS - 1);
        CP_WAIT(NS - 1);

        float v0[8], v1[8];
        load8h(v0, &abuf[w][s][0][l * 8]);
        load8h(v1, &abuf[w][s][1][l * 8]);

        float d0 = 0.f, d1 = 0.f;
#pragma unroll
        for (int j = 0; j < 8; j++) { d0 = fmaf(q8[j], v0[j], d0); d1 = fmaf(q8[j], v1[j], d1); }
        d0 = warp_sum(d0);
        d1 = warp_sum(d1);

        const bool val1 = (2 * it + 1) < nrow;   // warp-uniform
        float sc0 = d0 * scale;
        float sc1 = val1 ? d1 * scale : -1e30f;
        float mn = fmaxf(m, fmaxf(sc0, sc1));
        float fac = __expf(m - mn);
        float e0 = __expf(sc0 - mn);
        float e1 = val1 ? __expf(sc1 - mn) : 0.0f;
        ssum = ssum * fac + e0 + e1;
        if (val1) {
#pragma unroll
            for (int j = 0; j < 8; j++)
                ctx[j] = fmaf(e1, v1[j], fmaf(e0, v0[j], ctx[j] * fac));
        } else {
#pragma unroll
            for (int j = 0; j < 8; j++)
                ctx[j] = fmaf(e0, v0[j], ctx[j] * fac);
        }
        m = mn;

        const int nit = it + NS;
        if (nit < npair) {
            const int i0 = 2 * nit, i1 = i0 + 1;
            CP_ASYNC16(smem_u32(&abuf[w][s][0][l * 8]),
                       attb + (size_t)(w + i0 * NW) * AA + l * 8);
            if (i1 < nrow)
                CP_ASYNC16(smem_u32(&abuf[w][s][1][l * 8]),
                           attb + (size_t)(w + i1 * NW) * AA + l * 8);
        }
        CP_COMMIT();
    }

    // merge 16 warps (cbuf aliases the ring — all warps are done with it)
    __syncthreads();
    *(float4*)&cbuf[w * AA + l * 8]     = make_float4(ctx[0], ctx[1], ctx[2], ctx[3]);
    *(float4*)&cbuf[w * AA + l * 8 + 4] = make_float4(ctx[4], ctx[5], ctx[6], ctx[7]);
    if (l == 0) { sm_m[w] = m; sm_s[w] = ssum; }
    __syncthreads();

    if (tid < AA) {
        const int a = tid;
        float M = -1e30f;
#pragma unroll
        for (int ww = 0; ww < NW; ww++) M = fmaxf(M, sm_m[ww]);
        float S = 0.f, C = 0.f;
#pragma unroll
        for (int ww = 0; ww < NW; ww++) {
            float ef = __expf(sm_m[ww] - M);
            S += ef * sm_s[ww];
            C = fmaf(ef, cbuf[ww * AA + a], C);
        }
        g_inp[b * KTOT + VV + a] = C / S;
    }
}

// ============================================================================
// Kernel 4: gates GEMM, split-K=8, register-prefetch double buffering.
// 64x64 tile, 256 threads, 4x4 per-thread, grid (4, 16, 8).
// ============================================================================
__global__ __launch_bounds__(256) void gates_kernel(const float* __restrict__ Wih,
                                                    const float* __restrict__ Whh) {
    __shared__ float sA[16][68];   // [k][m]
    __shared__ float sB[16][68];   // [k][n]
    const int bm = blockIdx.x * 64;
    const int bn = blockIdx.y * 64;
    const int z  = blockIdx.z;
    const int tid = threadIdx.x;
    const int tm = tid & 15;
    const int tn = tid >> 4;
    const int lrow = tid >> 2;     // 0..63
    const int kc   = tid & 3;      // k-quad within panel

    float acc[4][4] = {};
    float4 aReg, bReg;

    auto load_panel = [&](int k0) {
        int k = k0 + kc * 4;
        if (k + 3 < KTOT) {
            aReg = *(const float4*)&g_inp[(bm + lrow) * KTOT + k];
            if (k + 3 < KIH)
                bReg = *(const float4*)&Wih[(size_t)(bn + lrow) * KIH + k];
            else
                bReg = *(const float4*)&Whh[(size_t)(bn + lrow) * HH + (k - KIH)];
        } else {
            aReg = make_float4(0.f, 0.f, 0.f, 0.f);
            bReg = make_float4(0.f, 0.f, 0.f, 0.f);
        }
    };

    load_panel(z * 16);

    for (int panel = z; panel * 16 < KTOT; panel += SPK) {
        sA[kc * 4 + 0][lrow] = aReg.x; sA[kc * 4 + 1][lrow] = aReg.y;
        sA[kc * 4 + 2][lrow] = aReg.z; sA[kc * 4 + 3][lrow] = aReg.w;
        sB[kc * 4 + 0][lrow] = bReg.x; sB[kc * 4 + 1][lrow] = bReg.y;
        sB[kc * 4 + 2][lrow] = bReg.z; sB[kc * 4 + 3][lrow] = bReg.w;
        __syncthreads();

        if ((panel + SPK) * 16 < KTOT) load_panel((panel + SPK) * 16);

#pragma unroll
        for (int kk = 0; kk < 16; kk++) {
            float4 av = *(const float4*)&sA[kk][tm * 4];
            float4 bv = *(const float4*)&sB[kk][tn * 4];
            const float ar[4] = {av.x, av.y, av.z, av.w};
            const float br[4] = {bv.x, bv.y, bv.z, bv.w};
#pragma unroll
            for (int r = 0; r < 4; r++)
#pragma unroll
                for (int c = 0; c < 4; c++)
                    acc[r][c] = fmaf(ar[r], br[c], acc[r][c]);
        }
        __syncthreads();
    }

    float* gp = g_gpart[z];
#pragma unroll
    for (int r = 0; r < 4; r++) {
        int row = bm + tm * 4 + r;
        *(float4*)&gp[row * NG + bn + tn * 4] =
            make_float4(acc[r][0], acc[r][1], acc[r][2], acc[r][3]);
    }
}

// ============================================================================
// Kernel 5: combine split-K partials + biases, LSTM pointwise, output proj,
// and q_{t+1} = h2 @ Hc_w^T + Hc_b (fused — saves a kernel per step).
// ============================================================================
__global__ __launch_bounds__(256) void lstm_out_kernel(const float* __restrict__ bih,
                                                       const float* __restrict__ bhh,
                                                       const float* __restrict__ Cdw,
                                                       const float* __restrict__ Cdb,
                                                       const float* __restrict__ Hcw,
                                                       const float* __restrict__ Hcb,
                                                       float* __restrict__ out, int t) {
    const int b = blockIdx.x;
    const int tid = threadIdx.x;
    const int warp = tid >> 5, lane = tid & 31;
    __shared__ float sh2[HH];

    const int base = b * NG;
    float gi = bih[tid]       + bhh[tid];
    float gf = bih[256 + tid] + bhh[256 + tid];
    float gg = bih[512 + tid] + bhh[512 + tid];
    float go = bih[768 + tid] + bhh[768 + tid];
#pragma unroll
    for (int z = 0; z < SPK; z++) {
        const float* gp = g_gpart[z] + base;
        gi += gp[tid];
        gf += gp[256 + tid];
        gg += gp[512 + tid];
        go += gp[768 + tid];
    }

    float c2 = sigmoidf_(gf) * g_c[b * HH + tid] + sigmoidf_(gi) * tanhf(gg);
    float h2 = sigmoidf_(go) * tanhf(c2);
    g_c[b * HH + tid] = c2;
    g_inp[b * KTOT + KIH + tid] = h2;   // h for next step
    sh2[tid] = h2;
    __syncthreads();

    // q for the NEXT step: thread tid owns output n = tid
    {
        const float4* wr = (const float4*)(Hcw + (size_t)tid * HH);
        float qa = 0.f;
#pragma unroll 8
        for (int k4 = 0; k4 < HH / 4; k4++) {
            float4 wv = wr[k4];
            const float* hh = &sh2[k4 * 4];
            qa = fmaf(wv.x, hh[0], qa);
            qa = fmaf(wv.y, hh[1], qa);
            qa = fmaf(wv.z, hh[2], qa);
            qa = fmaf(wv.w, hh[3], qa);
        }
        g_q[b * AA + tid] = qa + Hcb[tid];
    }

    // out[b, t, v] ; warp-per-v for coalesced Cd_w reads
    for (int v = warp; v < VV; v += 8) {
        const float* wr = Cdw + (size_t)v * HH;
        float s = 0.0f;
#pragma unroll
        for (int k = lane; k < HH; k += 32) s += sh2[k] * wr[k];
        s = warp_sum(s);
        if (lane == 0) {
            float val = s + Cdb[v];
            out[((size_t)b * TT + t) * VV + v] = val;
            g_inp[b * KTOT + v] = val;  // x for next step
        }
    }
}

// ============================================================================
extern "C" void kernel_launch(void* const* d_in, const int* in_sizes, int n_in,
                              void* d_out, int out_size) {
    (void)in_sizes; (void)n_in; (void)out_size;
    const float* img  = (const float*)d_in[0];
    const float* tgt  = (const float*)d_in[1];
    const float* Icw  = (const float*)d_in[2];
    const float* Icb  = (const float*)d_in[3];
    const float* Hcw  = (const float*)d_in[4];
    const float* Hcb  = (const float*)d_in[5];
    const float* Wih  = (const float*)d_in[6];
    const float* Whh  = (const float*)d_in[7];
    const float* bih  = (const float*)d_in[8];
    const float* bhh  = (const float*)d_in[9];
    const float* Cdw  = (const float*)d_in[10];
    const float* Cdb  = (const float*)d_in[11];
    float* out = (float*)d_out;

    const int ATTN_SMEM = NW * NS * 2 * AA * (int)sizeof(__half);  // 64 KB
    cudaFuncSetAttribute(attn_kernel, cudaFuncAttributeMaxDynamicSharedMemorySize,
                         ATTN_SMEM);

    proj_kernel<<<(BB * PP) / 64, 256>>>(img, Icw, Icb);
    init_kernel<<<BB, 256>>>(tgt, Hcb);

    for (int t = 0; t < TT; t++) {
        attn_kernel<<<BB, 512, ATTN_SMEM>>>();
        gates_kernel<<<dim3(BB / 64, NG / 64, SPK), 256>>>(Wih, Whh);
        lstm_out_kernel<<<BB, 256>>>(bih, bhh, Cdw, Cdb, Hcw, Hcb, out, t);
    }
}

// round 12
// speedup vs baseline: 2.0677x; 1.0858x over previous
#include <cuda_runtime.h>
#include <cuda_fp16.h>
#include <mma.h>
#include <math.h>
#include <stdint.h>

using namespace nvcuda;

#define BB 256
#define PP 620
#define CC 512
#define TT 32
#define VV 140
#define HH 256
#define AA 256
#define KIH (VV + AA)         // 396
#define KTOT (VV + AA + HH)   // 652 : [x | ctx | h]
#define NG   (4 * HH)         // 1024 gates
#define NS   4                // attention cp.async ring depth (pair-stages)
#define SPK  8                // gates split-K factor
#define GRID 148              // persistent CTAs (<= SM count, co-resident)

// ---------------- scratch (device globals; no allocations allowed) ----------
__device__ __half g_attn[(size_t)BB * PP * AA];   // 81.3 MB (fp16)
__device__ float  g_inp[BB * KTOT];               // packed [x | ctx | h]
__device__ float  g_c[BB * HH];
__device__ float  g_q[BB * AA];
__device__ float  g_gpart[SPK][BB * NG];          // split-K partials
__device__ unsigned g_tix[TT * 4];                // grid-barrier tickets (monotonic)

// ---------------- helpers ----------------
__device__ __forceinline__ float warp_sum(float v) {
#pragma unroll
    for (int o = 16; o > 0; o >>= 1) v += __shfl_xor_sync(0xFFFFFFFFu, v, o);
    return v;
}
__device__ __forceinline__ float sigmoidf_(float x) { return 1.0f / (1.0f + __expf(-x)); }
__device__ __forceinline__ unsigned smem_u32(const void* p) {
    return (unsigned)__cvta_generic_to_shared(p);
}
__device__ __forceinline__ void load8h(float* v, const __half* p) {
    uint4 u = *(const uint4*)p;
    float2 f;
    f = __half22float2(*reinterpret_cast<__half2*>(&u.x)); v[0] = f.x; v[1] = f.y;
    f = __half22float2(*reinterpret_cast<__half2*>(&u.y)); v[2] = f.x; v[3] = f.y;
    f = __half22float2(*reinterpret_cast<__half2*>(&u.z)); v[4] = f.x; v[5] = f.y;
    f = __half22float2(*reinterpret_cast<__half2*>(&u.w)); v[6] = f.x; v[7] = f.y;
}

#define CP_ASYNC16(dst32, src) \
    asm volatile("cp.async.cg.shared.global [%0], [%1], 16;" :: "r"(dst32), "l"(src))
#define CP_COMMIT() asm volatile("cp.async.commit_group;")
#define CP_WAIT(N)  asm volatile("cp.async.wait_group %0;" :: "n"(N))
// named barrier over one 256-thread half (ids 1 and 2; 0 is __syncthreads)
#define NB(half) asm volatile("bar.sync %0, 256;" :: "r"((half) + 1) : "memory")

// Grid-wide barrier: monotonic ticket per slot — safe across graph replays.
__device__ __forceinline__ void grid_barrier(int slot) {
    __syncthreads();
    if (threadIdx.x == 0) {
        __threadfence();
        unsigned t = atomicAdd(&g_tix[slot], 1u);
        unsigned target = (t / GRID + 1u) * GRID;
        while (*((volatile unsigned*)&g_tix[slot]) < target) {}
    }
    __syncthreads();
}

// ============================================================================
// Kernel 1: projection  attn[m, a] = sum_c img[m, c] * Ic_w[a, c] + Ic_b[a]
// Tile 64M x 256N (img read once), double-buffered cp.async, tf32 wmma.
// ============================================================================
__global__ __launch_bounds__(256) void proj_kernel(const float* __restrict__ img,
                                                   const float* __restrict__ Icw,
                                                   const float* __restrict__ Icb) {
    __shared__ float smA[2][64 * 16];
    __shared__ float smB[2][256 * 16];
    __shared__ float patch[8][16 * 16];

    const int bm = blockIdx.x * 64;
    const int tid = threadIdx.x;
    const int warp = tid >> 5, lane = tid & 31;
    const int NKS = CC / 16;

    auto issue = [&](int ks, int buf) {
        const int k0 = ks * 16;
        {
            int r = tid >> 2, q = tid & 3;
            CP_ASYNC16(smem_u32(&smA[buf][r * 16 + q * 4]),
                       img + (size_t)(bm + r) * CC + k0 + q * 4);
        }
#pragma unroll
        for (int i = 0; i < 4; i++) {
            int idx = tid + i * 256;
            int n = idx >> 2, q = idx & 3;
            CP_ASYNC16(smem_u32(&smB[buf][n * 16 + q * 4]),
                       Icw + (size_t)n * CC + k0 + q * 4);
        }
        CP_COMMIT();
    };

    wmma::fragment<wmma::accumulator, 16, 16, 8, float> acc[4][2];
#pragma unroll
    for (int mi = 0; mi < 4; mi++)
#pragma unroll
        for (int nj = 0; nj < 2; nj++) wmma::fill_fragment(acc[mi][nj], 0.0f);

    issue(0, 0);
    issue(1, 1);

    for (int ks = 0; ks < NKS; ks++) {
        if (ks + 1 < NKS) { CP_WAIT(1); } else { CP_WAIT(0); }
        __syncthreads();
        const int buf = ks & 1;
#pragma unroll
        for (int kk = 0; kk < 16; kk += 8) {
            wmma::fragment<wmma::matrix_a, 16, 16, 8, wmma::precision::tf32, wmma::row_major> fa[4];
#pragma unroll
            for (int mi = 0; mi < 4; mi++)
                wmma::load_matrix_sync(fa[mi], &smA[buf][(mi * 16) * 16 + kk], 16);
#pragma unroll
            for (int nj = 0; nj < 2; nj++) {
                wmma::fragment<wmma::matrix_b, 16, 16, 8, wmma::precision::tf32, wmma::col_major> fb;
                wmma::load_matrix_sync(fb, &smB[buf][(warp * 32 + nj * 16) * 16 + kk], 16);
#pragma unroll
                for (int mi = 0; mi < 4; mi++)
                    wmma::mma_sync(acc[mi][nj], fa[mi], fb, acc[mi][nj]);
            }
        }
        __syncthreads();
        if (ks + 2 < NKS) issue(ks + 2, buf);
    }

    const int prow = lane >> 1, pc0 = (lane & 1) * 8;
#pragma unroll
    for (int mi = 0; mi < 4; mi++) {
#pragma unroll
        for (int nj = 0; nj < 2; nj++) {
            wmma::store_matrix_sync(&patch[warp][0], acc[mi][nj], 16, wmma::mem_row_major);
            __syncwarp();
            const int gm = bm + mi * 16 + prow;
            const int gc = warp * 32 + nj * 16 + pc0;
            __half2 h2s[4];
#pragma unroll
            for (int j = 0; j < 4; j++) {
                float v0 = patch[warp][prow * 16 + pc0 + 2 * j]     + Icb[gc + 2 * j];
                float v1 = patch[warp][prow * 16 + pc0 + 2 * j + 1] + Icb[gc + 2 * j + 1];
                h2s[j] = __floats2half2_rn(v0, v1);
            }
            *(uint4*)&g_attn[(size_t)gm * AA + gc] = *(uint4*)h2s;
            __syncwarp();
        }
    }
}

// ============================================================================
// Kernel 2: init  g_inp = [x0 | 0 | 0], c = 0.
// ============================================================================
__global__ void init_kernel(const float* __restrict__ targets) {
    const int b = blockIdx.x;
    const int tid = threadIdx.x;
    for (int k = tid; k < KTOT; k += 256)
        g_inp[b * KTOT + k] = (k < VV) ? targets[(size_t)b * TT * VV + k] : 0.0f;
    g_c[b * HH + tid] = 0.0f;
}

// ============================================================================
// MEGAKERNEL phases.  148 CTAs x 512 threads, two independent 256-thread
// halves per CTA.  Cross-SM mutable data read via __ldcg (L1 not coherent
// inside one kernel).
// ============================================================================

// --- phase Q: q = h @ Hcw^T + Hcb.  32x32 tiles, 64 units (ctas 0..31) ---
__device__ __forceinline__ void q_phase(const float* __restrict__ Hcw,
                                        const float* __restrict__ Hcb,
                                        char* dynsm) {
    const int half = threadIdx.x >> 8;
    const int t2 = threadIdx.x & 255;
    const int u = blockIdx.x * 2 + half;
    if (u >= 64) return;
    float* sH = (float*)(dynsm + half * 20480);  // [64][33]
    float* sW = sH + 64 * 33;                    // [64][33]
    const int bm = (u >> 3) * 32;
    const int bn = (u & 7) * 32;
    const int a = t2 & 31;
    const int mg = t2 >> 5;

    float acc[4] = {0.f, 0.f, 0.f, 0.f};
    for (int k0 = 0; k0 < HH; k0 += 64) {
#pragma unroll
        for (int i = 0; i < 2; i++) {
            int qi = t2 + i * 256;
            int mm = qi >> 4, kq = qi & 15;
            float4 hv = __ldcg((const float4*)&g_inp[(bm + mm) * KTOT + KIH + k0 + kq * 4]);
            float4 wv = *(const float4*)&Hcw[(size_t)(bn + mm) * HH + k0 + kq * 4];
            sH[(kq * 4 + 0) * 33 + mm] = hv.x; sH[(kq * 4 + 1) * 33 + mm] = hv.y;
            sH[(kq * 4 + 2) * 33 + mm] = hv.z; sH[(kq * 4 + 3) * 33 + mm] = hv.w;
            sW[(kq * 4 + 0) * 33 + mm] = wv.x; sW[(kq * 4 + 1) * 33 + mm] = wv.y;
            sW[(kq * 4 + 2) * 33 + mm] = wv.z; sW[(kq * 4 + 3) * 33 + mm] = wv.w;
        }
        NB(half);
#pragma unroll
        for (int kk = 0; kk < 64; kk++) {
            float w = sW[kk * 33 + a];
#pragma unroll
            for (int r = 0; r < 4; r++)
                acc[r] = fmaf(sH[kk * 33 + mg * 4 + r], w, acc[r]);
        }
        NB(half);
    }
    float bias = Hcb[bn + a];
#pragma unroll
    for (int r = 0; r < 4; r++)
        g_q[(bm + mg * 4 + r) * AA + bn + a] = acc[r] + bias;
}

// --- phase A: attention.  ctas 0..127; half h handles b = cta*2 + h with
// 8 warps.  Warp wg owns rows p = wg + 8i.  Per-warp 4-deep cp.async ring. ---
__device__ __forceinline__ void attn_phase(char* dynsm, float* sm_m, float* sm_s) {
    const int cta = blockIdx.x;
    if (cta >= 128) return;
    const int tid = threadIdx.x;
    const int w = tid >> 5, l = tid & 31;
    const int half = w >> 3, wg = w & 7;
    const int b = cta * 2 + half;
    const __half* attb = g_attn + (size_t)b * PP * AA;
    __half* ring = (__half*)dynsm + w * (NS * 2 * AA);   // [NS][2][AA]

    const int nrow = (PP - wg + 7) >> 3;   // 78 (wg<4) or 77
    const int npair = 39;

#pragma unroll
    for (int it = 0; it < NS; it++) {
        CP_ASYNC16(smem_u32(ring + (it * 2 + 0) * AA + l * 8),
                   attb + (size_t)(wg + (2 * it) * 8) * AA + l * 8);
        CP_ASYNC16(smem_u32(ring + (it * 2 + 1) * AA + l * 8),
                   attb + (size_t)(wg + (2 * it + 1) * 8) * AA + l * 8);
        CP_COMMIT();
    }

    float q8[8];
    {
        float4 qa = __ldcg((const float4*)&g_q[b * AA + l * 8]);
        float4 qb = __ldcg((const float4*)&g_q[b * AA + l * 8 + 4]);
        q8[0] = qa.x; q8[1] = qa.y; q8[2] = qa.z; q8[3] = qa.w;
        q8[4] = qb.x; q8[5] = qb.y; q8[6] = qb.z; q8[7] = qb.w;
    }

    const float scale = 0.0625f;
    float m = -1e30f, ssum = 0.0f;
    float ctx[8] = {0.f, 0.f, 0.f, 0.f, 0.f, 0.f, 0.f, 0.f};

    for (int it = 0; it < npair; it++) {
        const int s = it & (NS - 1);
        CP_WAIT(NS - 1);

        float v0[8], v1[8];
        load8h(v0, ring + (s * 2 + 0) * AA + l * 8);
        load8h(v1, ring + (s * 2 + 1) * AA + l * 8);

        float d0 = 0.f, d1 = 0.f;
#pragma unroll
        for (int j = 0; j < 8; j++) { d0 = fmaf(q8[j], v0[j], d0); d1 = fmaf(q8[j], v1[j], d1); }
        d0 = warp_sum(d0);
        d1 = warp_sum(d1);

        const bool val1 = (2 * it + 1) < nrow;
        float sc0 = d0 * scale;
        float sc1 = val1 ? d1 * scale : -1e30f;
        float mn = fmaxf(m, fmaxf(sc0, sc1));
        float fac = __expf(m - mn);
        float e0 = __expf(sc0 - mn);
        float e1 = val1 ? __expf(sc1 - mn) : 0.0f;
        ssum = ssum * fac + e0 + e1;
        if (val1) {
#pragma unroll
            for (int j = 0; j < 8; j++)
                ctx[j] = fmaf(e1, v1[j], fmaf(e0, v0[j], ctx[j] * fac));
        } else {
#pragma unroll
            for (int j = 0; j < 8; j++)
                ctx[j] = fmaf(e0, v0[j], ctx[j] * fac);
        }
        m = mn;

        const int nit = it + NS;
        if (nit < npair) {
            const int i0 = 2 * nit, i1 = i0 + 1;
            CP_ASYNC16(smem_u32(ring + (s * 2 + 0) * AA + l * 8),
                       attb + (size_t)(wg + i0 * 8) * AA + l * 8);
            if (i1 < nrow)
                CP_ASYNC16(smem_u32(ring + (s * 2 + 1) * AA + l * 8),
                           attb + (size_t)(wg + i1 * 8) * AA + l * 8);
        }
        CP_COMMIT();
    }
    CP_WAIT(0);

    NB(half);   // all 8 warps of this half done with their rings
    float* cbuf = (float*)(dynsm + half * 32768);  // overlays this half's rings
    *(float4*)&cbuf[wg * AA + l * 8]     = make_float4(ctx[0], ctx[1], ctx[2], ctx[3]);
    *(float4*)&cbuf[wg * AA + l * 8 + 4] = make_float4(ctx[4], ctx[5], ctx[6], ctx[7]);
    if (l == 0) { sm_m[w] = m; sm_s[w] = ssum; }
    NB(half);

    const int t2 = tid & 255;  // column a
    float M = -1e30f;
#pragma unroll
    for (int ww = 0; ww < 8; ww++) M = fmaxf(M, sm_m[half * 8 + ww]);
    float S = 0.f, C = 0.f;
#pragma unroll
    for (int ww = 0; ww < 8; ww++) {
        float ef = __expf(sm_m[half * 8 + ww] - M);
        S += ef * sm_s[half * 8 + ww];
        C = fmaf(ef, cbuf[ww * AA + t2], C);
    }
    g_inp[b * KTOT + VV + t2] = C / S;
}

// --- phase G: gates GEMM.  64m x 128n tiles, 4x8 per-thread, splitK=8.
// 256 units = ctas 0..127 x 2 halves, one round. ---
__device__ __forceinline__ void gates_phase(const float* __restrict__ Wih,
                                            const float* __restrict__ Whh,
                                            char* dynsm) {
    const int half = threadIdx.x >> 8;
    const int t2 = threadIdx.x & 255;
    const int u = blockIdx.x * 2 + half;
    if (u >= 256) return;
    const int z  = u & 7;
    const int bn = ((u >> 3) & 7) * 128;
    const int bm = (u >> 6) * 64;

    float* sA = (float*)(dynsm + half * 16384);  // [16][68]
    float* sB = sA + 16 * 68;                    // [16][132]
    const int tm = t2 & 15, tn = t2 >> 4;
    const int arow = t2 >> 2, akq = t2 & 3;

    float acc[4][8] = {};
    float4 aR, bR0, bR1;

    auto loadP = [&](int k0) {
        const float4 z4 = make_float4(0.f, 0.f, 0.f, 0.f);
        int ka = k0 + akq * 4;
        aR = (ka + 3 < KTOT) ? __ldcg((const float4*)&g_inp[(bm + arow) * KTOT + ka]) : z4;
#pragma unroll
        for (int i = 0; i < 2; i++) {
            int idx = t2 + i * 256;
            int n = bn + (idx >> 2);
            int kb = k0 + (idx & 3) * 4;
            float4 v = z4;
            if (kb + 3 < KTOT) {
                if (kb + 3 < KIH) v = *(const float4*)&Wih[(size_t)n * KIH + kb];
                else              v = *(const float4*)&Whh[(size_t)n * HH + (kb - KIH)];
            }
            if (i == 0) bR0 = v; else bR1 = v;
        }
    };

    loadP(z * 16);

    for (int panel = z; panel * 16 < KTOT; panel += SPK) {
        sA[(akq * 4 + 0) * 68 + arow] = aR.x; sA[(akq * 4 + 1) * 68 + arow] = aR.y;
        sA[(akq * 4 + 2) * 68 + arow] = aR.z; sA[(akq * 4 + 3) * 68 + arow] = aR.w;
#pragma unroll
        for (int i = 0; i < 2; i++) {
            int idx = t2 + i * 256;
            int nl = idx >> 2, kq = idx & 3;
            float4 v = (i == 0) ? bR0 : bR1;
            sB[(kq * 4 + 0) * 132 + nl] = v.x; sB[(kq * 4 + 1) * 132 + nl] = v.y;
            sB[(kq * 4 + 2) * 132 + nl] = v.z; sB[(kq * 4 + 3) * 132 + nl] = v.w;
        }
        NB(half);

        if ((panel + SPK) * 16 < KTOT) loadP((panel + SPK) * 16);

#pragma unroll
        for (int kk = 0; kk < 16; kk++) {
            float4 a4  = *(const float4*)&sA[kk * 68 + tm * 4];
            float4 b4a = *(const float4*)&sB[kk * 132 + tn * 8];
            float4 b4b = *(const float4*)&sB[kk * 132 + tn * 8 + 4];
            const float ar[4] = {a4.x, a4.y, a4.z, a4.w};
            const float br[8] = {b4a.x, b4a.y, b4a.z, b4a.w, b4b.x, b4b.y, b4b.z, b4b.w};
#pragma unroll
            for (int r = 0; r < 4; r++)
#pragma unroll
                for (int c = 0; c < 8; c++)
                    acc[r][c] = fmaf(ar[r], br[c], acc[r][c]);
        }
        NB(half);
    }

    float* gp = g_gpart[z];
#pragma unroll
    for (int r = 0; r < 4; r++) {
        int row = bm + tm * 4 + r;
        *(float4*)&gp[row * NG + bn + tn * 8] =
            make_float4(acc[r][0], acc[r][1], acc[r][2], acc[r][3]);
        *(float4*)&gp[row * NG + bn + tn * 8 + 4] =
            make_float4(acc[r][4], acc[r][5], acc[r][6], acc[r][7]);
    }
}

// --- phase L: combine partials + biases, LSTM pointwise, output proj. ---
__device__ __forceinline__ void lstm_phase(const float* __restrict__ bih,
                                           const float* __restrict__ bhh,
                                           const float* __restrict__ Cdw,
                                           const float* __restrict__ Cdb,
                                           float* __restrict__ out, int t,
                                           char* dynsm) {
    const int cta = blockIdx.x;
    if (cta >= 128) return;
    const int half = threadIdx.x >> 8;
    const int t2 = threadIdx.x & 255;
    const int b = cta * 2 + half;
    const int warp = t2 >> 5, lane = t2 & 31;
    float* sh2 = (float*)(dynsm + half * 4096);  // 256 floats

    const int base = b * NG;
    float gi = bih[t2]       + bhh[t2];
    float gf = bih[256 + t2] + bhh[256 + t2];
    float gg = bih[512 + t2] + bhh[512 + t2];
    float go = bih[768 + t2] + bhh[768 + t2];
#pragma unroll
    for (int z = 0; z < SPK; z++) {
        const float* gp = g_gpart[z] + base;
        gi += __ldcg(&gp[t2]);
        gf += __ldcg(&gp[256 + t2]);
        gg += __ldcg(&gp[512 + t2]);
        go += __ldcg(&gp[768 + t2]);
    }

    float c2 = sigmoidf_(gf) * g_c[b * HH + t2] + sigmoidf_(gi) * tanhf(gg);
    float h2 = sigmoidf_(go) * tanhf(c2);
    g_c[b * HH + t2] = c2;
    g_inp[b * KTOT + KIH + t2] = h2;
    sh2[t2] = h2;
    NB(half);

    for (int v = warp; v < VV; v += 8) {
        const float* wr = Cdw + (size_t)v * HH;
        float s = 0.0f;
#pragma unroll
        for (int k = lane; k < HH; k += 32) s += sh2[k] * wr[k];
        s = warp_sum(s);
        if (lane == 0) {
            float val = s + Cdb[v];
            out[((size_t)b * TT + t) * VV + v] = val;
            g_inp[b * KTOT + v] = val;
        }
    }
}

// ============================================================================
// MEGAKERNEL: all 32 steps, 4 phases/step, grid barriers between phases.
// ============================================================================
__global__ __launch_bounds__(512, 1) void mega_kernel(
    const float* __restrict__ Hcw, const float* __restrict__ Hcb,
    const float* __restrict__ Wih, const float* __restrict__ Whh,
    const float* __restrict__ bih, const float* __restrict__ bhh,
    const float* __restrict__ Cdw, const float* __restrict__ Cdb,
    float* __restrict__ out) {
    extern __shared__ __align__(16) char dynsm[];
    __shared__ float sm_m[16], sm_s[16];

    for (int t = 0; t < TT; t++) {
        q_phase(Hcw, Hcb, dynsm);
        grid_barrier(t * 4 + 0);
        attn_phase(dynsm, sm_m, sm_s);
        grid_barrier(t * 4 + 1);
        gates_phase(Wih, Whh, dynsm);
        grid_barrier(t * 4 + 2);
        lstm_phase(bih, bhh, Cdw, Cdb, out, t, dynsm);
        grid_barrier(t * 4 + 3);
    }
}

// ============================================================================
extern "C" void kernel_launch(void* const* d_in, const int* in_sizes, int n_in,
                              void* d_out, int out_size) {
    (void)in_sizes; (void)n_in; (void)out_size;
    const float* img  = (const float*)d_in[0];
    const float* tgt  = (const float*)d_in[1];
    const float* Icw  = (const float*)d_in[2];
    const float* Icb  = (const float*)d_in[3];
    const float* Hcw  = (const float*)d_in[4];
    const float* Hcb  = (const float*)d_in[5];
    const float* Wih  = (const float*)d_in[6];
    const float* Whh  = (const float*)d_in[7];
    const float* bih  = (const float*)d_in[8];
    const float* bhh  = (const float*)d_in[9];
    const float* Cdw  = (const float*)d_in[10];
    const float* Cdb  = (const float*)d_in[11];
    float* out = (float*)d_out;

    const int MEGA_SMEM = 65536;  // 64 KB dynamic
    cudaFuncSetAttribute(mega_kernel, cudaFuncAttributeMaxDynamicSharedMemorySize,
                         MEGA_SMEM);

    proj_kernel<<<(BB * PP) / 64, 256>>>(img, Icw, Icb);
    init_kernel<<<BB, 256>>>(tgt);
    mega_kernel<<<GRID, 512, MEGA_SMEM>>>(Hcw, Hcb, Wih, Whh, bih, bhh, Cdw, Cdb, out);
}

// round 13
// speedup vs baseline: 2.1144x; 1.0226x over previous
#include <cuda_runtime.h>
#include <cuda_fp16.h>
#include <mma.h>
#include <math.h>
#include <stdint.h>

using namespace nvcuda;

#define BB 256
#define PP 620
#define CC 512
#define TT 32
#define VV 140
#define HH 256
#define AA 256
#define KIH (VV + AA)         // 396
#define KTOT (VV + AA + HH)   // 652 : [x | ctx | h]
#define NG   (4 * HH)         // 1024 gates
#define NS   4                // attention cp.async ring depth (pair-stages)
#define SPK  8                // gates split-K factor
#define GRID 148              // persistent CTAs (<= SM count, co-resident)

// proj tiling
#define PLDM 20               // padded smem row stride (floats) — kills bank conflicts

// ---------------- scratch (device globals; no allocations allowed) ----------
__device__ __half g_attn[(size_t)BB * PP * AA];   // 81.3 MB (fp16)
__device__ float  g_inp[BB * KTOT];               // packed [x | ctx | h]
__device__ float  g_c[BB * HH];
__device__ float  g_q[BB * AA];
__device__ float  g_gpart[SPK][BB * NG];          // split-K partials
__device__ unsigned g_tix[TT * 4];                // grid-barrier tickets (monotonic)

// ---------------- helpers ----------------
__device__ __forceinline__ float warp_sum(float v) {
#pragma unroll
    for (int o = 16; o > 0; o >>= 1) v += __shfl_xor_sync(0xFFFFFFFFu, v, o);
    return v;
}
__device__ __forceinline__ float sigmoidf_(float x) { return 1.0f / (1.0f + __expf(-x)); }
__device__ __forceinline__ unsigned smem_u32(const void* p) {
    return (unsigned)__cvta_generic_to_shared(p);
}
__device__ __forceinline__ void load8h(float* v, const __half* p) {
    uint4 u = *(const uint4*)p;
    float2 f;
    f = __half22float2(*reinterpret_cast<__half2*>(&u.x)); v[0] = f.x; v[1] = f.y;
    f = __half22float2(*reinterpret_cast<__half2*>(&u.y)); v[2] = f.x; v[3] = f.y;
    f = __half22float2(*reinterpret_cast<__half2*>(&u.z)); v[4] = f.x; v[5] = f.y;
    f = __half22float2(*reinterpret_cast<__half2*>(&u.w)); v[6] = f.x; v[7] = f.y;
}

#define CP_ASYNC16(dst32, src) \
    asm volatile("cp.async.cg.shared.global [%0], [%1], 16;" :: "r"(dst32), "l"(src))
#define CP_COMMIT() asm volatile("cp.async.commit_group;")
#define CP_WAIT(N)  asm volatile("cp.async.wait_group %0;" :: "n"(N))
// named barrier over one 256-thread half (ids 1 and 2; 0 is __syncthreads)
#define NB(half) asm volatile("bar.sync %0, 256;" :: "r"((half) + 1) : "memory")

// Grid-wide barrier: monotonic ticket per slot — safe across graph replays.
__device__ __forceinline__ void grid_barrier(int slot) {
    __syncthreads();
    if (threadIdx.x == 0) {
        __threadfence();
        unsigned t = atomicAdd(&g_tix[slot], 1u);
        unsigned target = (t / GRID + 1u) * GRID;
        while (*((volatile unsigned*)&g_tix[slot]) < target) {}
    }
    __syncthreads();
}

// ============================================================================
// Kernel 1: projection  attn[m, a] = sum_c img[m, c] * Ic_w[a, c] + Ic_b[a]
// v2: 128M x 128N tiles (grid 1240 x 2), ldm=20 padded smem (conflict-free
// wmma loads), double-buffered cp.async, tf32 wmma.  8 warps in 4(m) x 2(n);
// each warp owns 32m x 64n = 2x4 fragments.
// Dynamic smem 40KB: smA[2] @ 0/2560, smB[2] @ 5120/7680 (floats);
// epilogue patch overlays smA[0].
// ============================================================================
__global__ __launch_bounds__(256) void proj_kernel(const float* __restrict__ img,
                                                   const float* __restrict__ Icw,
                                                   const float* __restrict__ Icb) {
    extern __shared__ __align__(16) float psm[];
    float* const smA0 = psm;
    float* const smA1 = psm + 2560;
    float* const smB0 = psm + 5120;
    float* const smB1 = psm + 7680;

    const int bm = blockIdx.x * 128;
    const int bn = blockIdx.y * 128;
    const int tid = threadIdx.x;
    const int warp = tid >> 5, lane = tid & 31;
    const int warp_m = warp & 3;   // 4 groups of 32 rows
    const int warp_n = warp >> 2;  // 2 groups of 64 cols
    const int NKS = CC / 16;       // 32 k-stages

    // per-stage loads: A 512 float4 + B 512 float4, 2+2 per thread
    auto issue = [&](int ks, int buf) {
        const int k0 = ks * 16;
        float* sA = buf ? smA1 : smA0;
        float* sB = buf ? smB1 : smB0;
#pragma unroll
        for (int j = 0; j < 2; j++) {
            int idx = tid + j * 256;
            int row = idx >> 2, q = idx & 3;
            CP_ASYNC16(smem_u32(&sA[row * PLDM + q * 4]),
                       img + (size_t)(bm + row) * CC + k0 + q * 4);
            CP_ASYNC16(smem_u32(&sB[row * PLDM + q * 4]),
                       Icw + (size_t)(bn + row) * CC + k0 + q * 4);
        }
        CP_COMMIT();
    };

    wmma::fragment<wmma::accumulator, 16, 16, 8, float> acc[2][4];
#pragma unroll
    for (int mi = 0; mi < 2; mi++)
#pragma unroll
        for (int nj = 0; nj < 4; nj++) wmma::fill_fragment(acc[mi][nj], 0.0f);

    issue(0, 0);
    issue(1, 1);

    for (int ks = 0; ks < NKS; ks++) {
        if (ks + 1 < NKS) { CP_WAIT(1); } else { CP_WAIT(0); }
        __syncthreads();
        const int buf = ks & 1;
        const float* sA = buf ? smA1 : smA0;
        const float* sB = buf ? smB1 : smB0;
#pragma unroll
        for (int kk = 0; kk < 16; kk += 8) {
            wmma::fragment<wmma::matrix_a, 16, 16, 8, wmma::precision::tf32, wmma::row_major> fa[2];
#pragma unroll
            for (int mi = 0; mi < 2; mi++)
                wmma::load_matrix_sync(fa[mi], &sA[(warp_m * 32 + mi * 16) * PLDM + kk], PLDM);
#pragma unroll
            for (int nj = 0; nj < 4; nj++) {
                wmma::fragment<wmma::matrix_b, 16, 16, 8, wmma::precision::tf32, wmma::col_major> fb;
                wmma::load_matrix_sync(fb, &sB[(warp_n * 64 + nj * 16) * PLDM + kk], PLDM);
#pragma unroll
                for (int mi = 0; mi < 2; mi++)
                    wmma::mma_sync(acc[mi][nj], fa[mi], fb, acc[mi][nj]);
            }
        }
        __syncthreads();
        if (ks + 2 < NKS) issue(ks + 2, buf);
    }

    // ---- epilogue: frag -> patch (overlays smA0) -> +bias -> fp16 global ----
    __syncthreads();
    float* patch = smA0 + warp * 256;   // 16x16 per warp
    const int prow = lane >> 1, pc0 = (lane & 1) * 8;
#pragma unroll
    for (int mi = 0; mi < 2; mi++) {
#pragma unroll
        for (int nj = 0; nj < 4; nj++) {
            wmma::store_matrix_sync(patch, acc[mi][nj], 16, wmma::mem_row_major);
            __syncwarp();
            const int gm = bm + warp_m * 32 + mi * 16 + prow;
            const int gc = bn + warp_n * 64 + nj * 16 + pc0;
            __half2 h2s[4];
#pragma unroll
            for (int j = 0; j < 4; j++) {
                float v0 = patch[prow * 16 + pc0 + 2 * j]     + Icb[gc + 2 * j];
                float v1 = patch[prow * 16 + pc0 + 2 * j + 1] + Icb[gc + 2 * j + 1];
                h2s[j] = __floats2half2_rn(v0, v1);
            }
            *(uint4*)&g_attn[(size_t)gm * AA + gc] = *(uint4*)h2s;
            __syncwarp();
        }
    }
}

// ============================================================================
// Kernel 2: init  g_inp = [x0 | 0 | 0], c = 0.
// ============================================================================
__global__ void init_kernel(const float* __restrict__ targets) {
    const int b = blockIdx.x;
    const int tid = threadIdx.x;
    for (int k = tid; k < KTOT; k += 256)
        g_inp[b * KTOT + k] = (k < VV) ? targets[(size_t)b * TT * VV + k] : 0.0f;
    g_c[b * HH + tid] = 0.0f;
}

// ============================================================================
// MEGAKERNEL phases.  148 CTAs x 512 threads, two independent 256-thread
// halves per CTA.  Cross-SM mutable data read via __ldcg (L1 not coherent
// inside one kernel).
// ============================================================================

// --- phase Q: q = h @ Hcw^T + Hcb.  32x32 tiles, 64 units (ctas 0..31) ---
__device__ __forceinline__ void q_phase(const float* __restrict__ Hcw,
                                        const float* __restrict__ Hcb,
                                        char* dynsm) {
    const int half = threadIdx.x >> 8;
    const int t2 = threadIdx.x & 255;
    const int u = blockIdx.x * 2 + half;
    if (u >= 64) return;
    float* sH = (float*)(dynsm + half * 20480);  // [64][33]
    float* sW = sH + 64 * 33;                    // [64][33]
    const int bm = (u >> 3) * 32;
    const int bn = (u & 7) * 32;
    const int a = t2 & 31;
    const int mg = t2 >> 5;

    float acc[4] = {0.f, 0.f, 0.f, 0.f};
    for (int k0 = 0; k0 < HH; k0 += 64) {
#pragma unroll
        for (int i = 0; i < 2; i++) {
            int qi = t2 + i * 256;
            int mm = qi >> 4, kq = qi & 15;
            float4 hv = __ldcg((const float4*)&g_inp[(bm + mm) * KTOT + KIH + k0 + kq * 4]);
            float4 wv = *(const float4*)&Hcw[(size_t)(bn + mm) * HH + k0 + kq * 4];
            sH[(kq * 4 + 0) * 33 + mm] = hv.x; sH[(kq * 4 + 1) * 33 + mm] = hv.y;
            sH[(kq * 4 + 2) * 33 + mm] = hv.z; sH[(kq * 4 + 3) * 33 + mm] = hv.w;
            sW[(kq * 4 + 0) * 33 + mm] = wv.x; sW[(kq * 4 + 1) * 33 + mm] = wv.y;
            sW[(kq * 4 + 2) * 33 + mm] = wv.z; sW[(kq * 4 + 3) * 33 + mm] = wv.w;
        }
        NB(half);
#pragma unroll
        for (int kk = 0; kk < 64; kk++) {
            float w = sW[kk * 33 + a];
#pragma unroll
            for (int r = 0; r < 4; r++)
                acc[r] = fmaf(sH[kk * 33 + mg * 4 + r], w, acc[r]);
        }
        NB(half);
    }
    float bias = Hcb[bn + a];
#pragma unroll
    for (int r = 0; r < 4; r++)
        g_q[(bm + mg * 4 + r) * AA + bn + a] = acc[r] + bias;
}

// --- phase A: attention.  ctas 0..127; half h handles b = cta*2 + h with
// 8 warps.  Warp wg owns rows p = wg + 8i.  Per-warp 4-deep cp.async ring. ---
__device__ __forceinline__ void attn_phase(char* dynsm, float* sm_m, float* sm_s) {
    const int cta = blockIdx.x;
    if (cta >= 128) return;
    const int tid = threadIdx.x;
    const int w = tid >> 5, l = tid & 31;
    const int half = w >> 3, wg = w & 7;
    const int b = cta * 2 + half;
    const __half* attb = g_attn + (size_t)b * PP * AA;
    __half* ring = (__half*)dynsm + w * (NS * 2 * AA);   // [NS][2][AA]

    const int nrow = (PP - wg + 7) >> 3;   // 78 (wg<4) or 77
    const int npair = 39;

#pragma unroll
    for (int it = 0; it < NS; it++) {
        CP_ASYNC16(smem_u32(ring + (it * 2 + 0) * AA + l * 8),
                   attb + (size_t)(wg + (2 * it) * 8) * AA + l * 8);
        CP_ASYNC16(smem_u32(ring + (it * 2 + 1) * AA + l * 8),
                   attb + (size_t)(wg + (2 * it + 1) * 8) * AA + l * 8);
        CP_COMMIT();
    }

    float q8[8];
    {
        float4 qa = __ldcg((const float4*)&g_q[b * AA + l * 8]);
        float4 qb = __ldcg((const float4*)&g_q[b * AA + l * 8 + 4]);
        q8[0] = qa.x; q8[1] = qa.y; q8[2] = qa.z; q8[3] = qa.w;
        q8[4] = qb.x; q8[5] = qb.y; q8[6] = qb.z; q8[7] = qb.w;
    }

    const float scale = 0.0625f;
    float m = -1e30f, ssum = 0.0f;
    float ctx[8] = {0.f, 0.f, 0.f, 0.f, 0.f, 0.f, 0.f, 0.f};

    for (int it = 0; it < npair; it++) {
        const int s = it & (NS - 1);
        CP_WAIT(NS - 1);

        float v0[8], v1[8];
        load8h(v0, ring + (s * 2 + 0) * AA + l * 8);
        load8h(v1, ring + (s * 2 + 1) * AA + l * 8);

        float d0 = 0.f, d1 = 0.f;
#pragma unroll
        for (int j = 0; j < 8; j++) { d0 = fmaf(q8[j], v0[j], d0); d1 = fmaf(q8[j], v1[j], d1); }
        d0 = warp_sum(d0);
        d1 = warp_sum(d1);

        const bool val1 = (2 * it + 1) < nrow;
        float sc0 = d0 * scale;
        float sc1 = val1 ? d1 * scale : -1e30f;
        float mn = fmaxf(m, fmaxf(sc0, sc1));
        float fac = __expf(m - mn);
        float e0 = __expf(sc0 - mn);
        float e1 = val1 ? __expf(sc1 - mn) : 0.0f;
        ssum = ssum * fac + e0 + e1;
        if (val1) {
#pragma unroll
            for (int j = 0; j < 8; j++)
                ctx[j] = fmaf(e1, v1[j], fmaf(e0, v0[j], ctx[j] * fac));
        } else {
#pragma unroll
            for (int j = 0; j < 8; j++)
                ctx[j] = fmaf(e0, v0[j], ctx[j] * fac);
        }
        m = mn;

        const int nit = it + NS;
        if (nit < npair) {
            const int i0 = 2 * nit, i1 = i0 + 1;
            CP_ASYNC16(smem_u32(ring + (s * 2 + 0) * AA + l * 8),
                       attb + (size_t)(wg + i0 * 8) * AA + l * 8);
            if (i1 < nrow)
                CP_ASYNC16(smem_u32(ring + (s * 2 + 1) * AA + l * 8),
                           attb + (size_t)(wg + i1 * 8) * AA + l * 8);
        }
        CP_COMMIT();
    }
    CP_WAIT(0);

    NB(half);   // all 8 warps of this half done with their rings
    float* cbuf = (float*)(dynsm + half * 32768);  // overlays this half's rings
    *(float4*)&cbuf[wg * AA + l * 8]     = make_float4(ctx[0], ctx[1], ctx[2], ctx[3]);
    *(float4*)&cbuf[wg * AA + l * 8 + 4] = make_float4(ctx[4], ctx[5], ctx[6], ctx[7]);
    if (l == 0) { sm_m[w] = m; sm_s[w] = ssum; }
    NB(half);

    const int t2 = tid & 255;  // column a
    float M = -1e30f;
#pragma unroll
    for (int ww = 0; ww < 8; ww++) M = fmaxf(M, sm_m[half * 8 + ww]);
    float S = 0.f, C = 0.f;
#pragma unroll
    for (int ww = 0; ww < 8; ww++) {
        float ef = __expf(sm_m[half * 8 + ww] - M);
        S += ef * sm_s[half * 8 + ww];
        C = fmaf(ef, cbuf[ww * AA + t2], C);
    }
    g_inp[b * KTOT + VV + t2] = C / S;
}

// --- phase G: gates GEMM.  64m x 128n tiles, 4x8 per-thread, splitK=8.
// 256 units = ctas 0..127 x 2 halves, one round. ---
__device__ __forceinline__ void gates_phase(const float* __restrict__ Wih,
                                            const float* __restrict__ Whh,
                                            char* dynsm) {
    const int half = threadIdx.x >> 8;
    const int t2 = threadIdx.x & 255;
    const int u = blockIdx.x * 2 + half;
    if (u >= 256) return;
    const int z  = u & 7;
    const int bn = ((u >> 3) & 7) * 128;
    const int bm = (u >> 6) * 64;

    float* sA = (float*)(dynsm + half * 16384);  // [16][68]
    float* sB = sA + 16 * 68;                    // [16][132]
    const int tm = t2 & 15, tn = t2 >> 4;
    const int arow = t2 >> 2, akq = t2 & 3;

    float acc[4][8] = {};
    float4 aR, bR0, bR1;

    auto loadP = [&](int k0) {
        const float4 z4 = make_float4(0.f, 0.f, 0.f, 0.f);
        int ka = k0 + akq * 4;
        aR = (ka + 3 < KTOT) ? __ldcg((const float4*)&g_inp[(bm + arow) * KTOT + ka]) : z4;
#pragma unroll
        for (int i = 0; i < 2; i++) {
            int idx = t2 + i * 256;
            int n = bn + (idx >> 2);
            int kb = k0 + (idx & 3) * 4;
            float4 v = z4;
            if (kb + 3 < KTOT) {
                if (kb + 3 < KIH) v = *(const float4*)&Wih[(size_t)n * KIH + kb];
                else              v = *(const float4*)&Whh[(size_t)n * HH + (kb - KIH)];
            }
            if (i == 0) bR0 = v; else bR1 = v;
        }
    };

    loadP(z * 16);

    for (int panel = z; panel * 16 < KTOT; panel += SPK) {
        sA[(akq * 4 + 0) * 68 + arow] = aR.x; sA[(akq * 4 + 1) * 68 + arow] = aR.y;
        sA[(akq * 4 + 2) * 68 + arow] = aR.z; sA[(akq * 4 + 3) * 68 + arow] = aR.w;
#pragma unroll
        for (int i = 0; i < 2; i++) {
            int idx = t2 + i * 256;
            int nl = idx >> 2, kq = idx & 3;
            float4 v = (i == 0) ? bR0 : bR1;
            sB[(kq * 4 + 0) * 132 + nl] = v.x; sB[(kq * 4 + 1) * 132 + nl] = v.y;
            sB[(kq * 4 + 2) * 132 + nl] = v.z; sB[(kq * 4 + 3) * 132 + nl] = v.w;
        }
        NB(half);

        if ((panel + SPK) * 16 < KTOT) loadP((panel + SPK) * 16);

#pragma unroll
        for (int kk = 0; kk < 16; kk++) {
            float4 a4  = *(const float4*)&sA[kk * 68 + tm * 4];
            float4 b4a = *(const float4*)&sB[kk * 132 + tn * 8];
            float4 b4b = *(const float4*)&sB[kk * 132 + tn * 8 + 4];
            const float ar[4] = {a4.x, a4.y, a4.z, a4.w};
            const float br[8] = {b4a.x, b4a.y, b4a.z, b4a.w, b4b.x, b4b.y, b4b.z, b4b.w};
#pragma unroll
            for (int r = 0; r < 4; r++)
#pragma unroll
                for (int c = 0; c < 8; c++)
                    acc[r][c] = fmaf(ar[r], br[c], acc[r][c]);
        }
        NB(half);
    }

    float* gp = g_gpart[z];
#pragma unroll
    for (int r = 0; r < 4; r++) {
        int row = bm + tm * 4 + r;
        *(float4*)&gp[row * NG + bn + tn * 8] =
            make_float4(acc[r][0], acc[r][1], acc[r][2], acc[r][3]);
        *(float4*)&gp[row * NG + bn + tn * 8 + 4] =
            make_float4(acc[r][4], acc[r][5], acc[r][6], acc[r][7]);
    }
}

// --- phase L: combine partials + biases, LSTM pointwise, output proj. ---
__device__ __forceinline__ void lstm_phase(const float* __restrict__ bih,
                                           const float* __restrict__ bhh,
                                           const float* __restrict__ Cdw,
                                           const float* __restrict__ Cdb,
                                           float* __restrict__ out, int t,
                                           char* dynsm) {
    const int cta = blockIdx.x;
    if (cta >= 128) return;
    const int half = threadIdx.x >> 8;
    const int t2 = threadIdx.x & 255;
    const int b = cta * 2 + half;
    const int warp = t2 >> 5, lane = t2 & 31;
    float* sh2 = (float*)(dynsm + half * 4096);  // 256 floats

    const int base = b * NG;
    float gi = bih[t2]       + bhh[t2];
    float gf = bih[256 + t2] + bhh[256 + t2];
    float gg = bih[512 + t2] + bhh[512 + t2];
    float go = bih[768 + t2] + bhh[768 + t2];
#pragma unroll
    for (int z = 0; z < SPK; z++) {
        const float* gp = g_gpart[z] + base;
        gi += __ldcg(&gp[t2]);
        gf += __ldcg(&gp[256 + t2]);
        gg += __ldcg(&gp[512 + t2]);
        go += __ldcg(&gp[768 + t2]);
    }

    float c2 = sigmoidf_(gf) * g_c[b * HH + t2] + sigmoidf_(gi) * tanhf(gg);
    float h2 = sigmoidf_(go) * tanhf(c2);
    g_c[b * HH + t2] = c2;
    g_inp[b * KTOT + KIH + t2] = h2;
    sh2[t2] = h2;
    NB(half);

    for (int v = warp; v < VV; v += 8) {
        const float* wr = Cdw + (size_t)v * HH;
        float s = 0.0f;
#pragma unroll
        for (int k = lane; k < HH; k += 32) s += sh2[k] * wr[k];
        s = warp_sum(s);
        if (lane == 0) {
            float val = s + Cdb[v];
            out[((size_t)b * TT + t) * VV + v] = val;
            g_inp[b * KTOT + v] = val;
        }
    }
}

// ============================================================================
// MEGAKERNEL: all 32 steps, 4 phases/step, grid barriers between phases.
// ============================================================================
__global__ __launch_bounds__(512, 1) void mega_kernel(
    const float* __restrict__ Hcw, const float* __restrict__ Hcb,
    const float* __restrict__ Wih, const float* __restrict__ Whh,
    const float* __restrict__ bih, const float* __restrict__ bhh,
    const float* __restrict__ Cdw, const float* __restrict__ Cdb,
    float* __restrict__ out) {
    extern __shared__ __align__(16) char dynsm[];
    __shared__ float sm_m[16], sm_s[16];

    for (int t = 0; t < TT; t++) {
        q_phase(Hcw, Hcb, dynsm);
        grid_barrier(t * 4 + 0);
        attn_phase(dynsm, sm_m, sm_s);
        grid_barrier(t * 4 + 1);
        gates_phase(Wih, Whh, dynsm);
        grid_barrier(t * 4 + 2);
        lstm_phase(bih, bhh, Cdw, Cdb, out, t, dynsm);
        grid_barrier(t * 4 + 3);
    }
}

// ============================================================================
extern "C" void kernel_launch(void* const* d_in, const int* in_sizes, int n_in,
                              void* d_out, int out_size) {
    (void)in_sizes; (void)n_in; (void)out_size;
    const float* img  = (const float*)d_in[0];
    const float* tgt  = (const float*)d_in[1];
    const float* Icw  = (const float*)d_in[2];
    const float* Icb  = (const float*)d_in[3];
    const float* Hcw  = (const float*)d_in[4];
    const float* Hcb  = (const float*)d_in[5];
    const float* Wih  = (const float*)d_in[6];
    const float* Whh  = (const float*)d_in[7];
    const float* bih  = (const float*)d_in[8];
    const float* bhh  = (const float*)d_in[9];
    const float* Cdw  = (const float*)d_in[10];
    const float* Cdb  = (const float*)d_in[11];
    float* out = (float*)d_out;

    const int PROJ_SMEM = 10240 * (int)sizeof(float);  // 40 KB dynamic
    cudaFuncSetAttribute(proj_kernel, cudaFuncAttributeMaxDynamicSharedMemorySize,
                         PROJ_SMEM);
    const int MEGA_SMEM = 65536;  // 64 KB dynamic
    cudaFuncSetAttribute(mega_kernel, cudaFuncAttributeMaxDynamicSharedMemorySize,
                         MEGA_SMEM);

    proj_kernel<<<dim3((BB * PP) / 128, AA / 128), 256, PROJ_SMEM>>>(img, Icw, Icb);
    init_kernel<<<BB, 256>>>(tgt);
    mega_kernel<<<GRID, 512, MEGA_SMEM>>>(Hcw, Hcb, Wih, Whh, bih, bhh, Cdw, Cdb, out);
}